// round 4
// baseline (speedup 1.0000x reference)
#include <cuda_runtime.h>
#include <math.h>

#define N_NODES 100000
#define N_EDGES 1600000

// ---------------- device scratch ----------------
__device__ float g_hA [N_NODES * 32];
__device__ float g_hB [N_NODES * 64];
__device__ float g_m  [N_NODES * 64];
__device__ float g_agg[N_NODES * 64];
__device__ float g_gi [N_NODES * 192];
__device__ float g_gh [N_NODES * 192];
__device__ float g_hid[N_NODES * 128];
__device__ float g_WT1ih[32 * 96];
__device__ float g_WT1hh[32 * 96];
__device__ float g_WT2ih[64 * 192];
__device__ float g_WT2hh[64 * 192];
__device__ float g_fc1T[64 * 128];
__device__ float g_fc2T[128 * 10];
__device__ int   g_ei32[2 * N_EDGES];
__device__ int   g_deg [N_NODES];
__device__ int   g_rowptr[N_NODES + 1];
__device__ int   g_cursor[N_NODES];
__device__ int   g_esrc[N_EDGES];
__device__ float g_ews [N_EDGES];
__device__ int   g_is64;

// ---------------- helpers ----------------
__device__ __forceinline__ float sigmoidf_(float x) { return 1.0f / (1.0f + expf(-x)); }
__device__ __forceinline__ float eluf_(float x)     { return x > 0.f ? x : expm1f(x); }

#define FMA2(d, a, b, c) \
    asm("fma.rn.f32x2 %0, %1, %2, %3;" : "=l"(d) : "l"(a), "l"(b), "l"(c))

__device__ __forceinline__ void unpack2(unsigned long long v, float& lo, float& hi) {
    asm("mov.b64 {%0, %1}, %2;" : "=f"(lo), "=f"(hi) : "l"(v));
}

// ---------------- edge-index dtype sniff + normalize ----------------
__global__ void k_sniff(const void* __restrict__ p) {
    __shared__ int s_bad;
    if (threadIdx.x == 0) s_bad = 0;
    __syncthreads();
    long long v = ((const long long*)p)[threadIdx.x];
    if (v < 0 || v >= N_NODES) atomicAdd(&s_bad, 1);
    __syncthreads();
    if (threadIdx.x == 0) g_is64 = (s_bad < 512) ? 1 : 0;
}

__global__ void k_convert(const void* __restrict__ p, int* __restrict__ out) {
    int i = blockIdx.x * blockDim.x + threadIdx.x;
    if (i >= 2 * N_EDGES) return;
    out[i] = g_is64 ? (int)((const long long*)p)[i] : ((const int*)p)[i];
}

// ---------------- CSR build ----------------
__global__ void k_zero_i(int* __restrict__ p, int n) {
    int i = blockIdx.x * blockDim.x + threadIdx.x;
    if (i < n) p[i] = 0;
}

__global__ void k_count(const int* __restrict__ ei, int* __restrict__ deg) {
    int e = blockIdx.x * blockDim.x + threadIdx.x;
    if (e >= N_EDGES) return;
    int d = ei[N_EDGES + e];
    if ((unsigned)d < N_NODES) atomicAdd(&deg[d], 1);
}

__global__ void k_scan(const int* __restrict__ deg, int* __restrict__ rowptr) {
    __shared__ int s[1024];
    __shared__ int s_off;
    int tid = threadIdx.x;
    if (tid == 0) s_off = 0;
    for (int base = 0; base < N_NODES; base += 1024) {
        int i = base + tid;
        int v = (i < N_NODES) ? deg[i] : 0;
        __syncthreads();
        s[tid] = v;
        __syncthreads();
        for (int d = 1; d < 1024; d <<= 1) {
            int t = (tid >= d) ? s[tid - d] : 0;
            __syncthreads();
            s[tid] += t;
            __syncthreads();
        }
        if (i < N_NODES) rowptr[i] = s_off + s[tid] - v;
        int total = s[1023];
        __syncthreads();
        if (tid == 0) s_off += total;
    }
    __syncthreads();
    if (tid == 0) rowptr[N_NODES] = s_off;
}

__global__ void k_copy_i(const int* __restrict__ a, int* __restrict__ b, int n) {
    int i = blockIdx.x * blockDim.x + threadIdx.x;
    if (i < n) b[i] = a[i];
}

__global__ void k_place(const int* __restrict__ ei, const float* __restrict__ ea,
                        int* __restrict__ cursor, int* __restrict__ esrc,
                        float* __restrict__ ews) {
    int e = blockIdx.x * blockDim.x + threadIdx.x;
    if (e >= N_EDGES) return;
    int s = ei[e];
    int d = ei[N_EDGES + e];
    if ((unsigned)s >= N_NODES || (unsigned)d >= N_NODES) return;
    int pos = atomicAdd(&cursor[d], 1);
    esrc[pos] = s;
    ews[pos]  = ea[e];
}

// ---------------- init / elementwise ----------------
__global__ void k_transpose(const float* __restrict__ W, float* __restrict__ WT, int R, int K) {
    int idx = blockIdx.x * blockDim.x + threadIdx.x;
    if (idx < R * K) { int r = idx / K, k = idx - r * K; WT[k * R + r] = W[idx]; }
}

__global__ void k_init_h(const float* __restrict__ x, float* __restrict__ h) {
    int i = blockIdx.x * blockDim.x + threadIdx.x;
    if (i < N_NODES * 32) {
        int n = i >> 5, c = i & 31;
        h[i] = (c < 16) ? x[n * 16 + c] : 0.f;
    }
}

__global__ void k_pad_elu(const float* __restrict__ src, float* __restrict__ dst) {
    int i = blockIdx.x * blockDim.x + threadIdx.x;
    if (i < N_NODES * 64) {
        int n = i >> 6, c = i & 63;
        dst[i] = (c < 32) ? eluf_(src[n * 32 + c]) : 0.f;
    }
}

// ---------------- f32x2 tiled GEMM ----------------
// Y[n, r0+c] = act( bias + sum_k X[n,k] * WT[k*R + r0+c] ), X optionally elu'd.
// Block tile: NT=128 nodes x RT cols. Thread: 8 nodes (4 f32x2 pairs) x 4 cols.
// A staged transposed (node-pairs -> LDS.64), weights duplicated (w,w) -> LDS.64.
template <int K, int RT, int NT>
__global__ void __launch_bounds__((NT / 8) * (RT / 4))
k_gemm2(const float* __restrict__ X, const float* __restrict__ WT,
        const float* __restrict__ bias, float* __restrict__ Y,
        int N, int R, int act, int in_act) {
    extern __shared__ char smem[];
    const int AST = NT + 2;                       // padded row stride (floats)
    float*  sAT = (float*)smem;                   // [K][AST]
    float2* sWd = (float2*)(smem + (size_t)K * AST * sizeof(float));  // [K][RT]
    const int NTH = (NT / 8) * (RT / 4);
    int tid = threadIdx.x;
    int n0  = blockIdx.x * NT;
    int r0  = blockIdx.y * RT;

    for (int i = tid; i < NT * K; i += NTH) {
        int n = i / K, k = i - n * K;
        int nn = n0 + n;
        float v = (nn < N) ? X[(size_t)nn * K + k] : 0.f;
        if (in_act) v = eluf_(v);
        sAT[k * AST + n] = v;
    }
    for (int i = tid; i < K * RT; i += NTH) {
        int k = i / RT, r = i - k * RT;
        float w = WT[(size_t)k * R + r0 + r];
        sWd[k * RT + r] = make_float2(w, w);
    }
    __syncthreads();

    int tc = tid % (RT / 4);
    int tn = tid / (RT / 4);
    int cb = tc * 4, nb = tn * 8;

    unsigned long long acc[4][4];
#pragma unroll
    for (int p = 0; p < 4; p++)
#pragma unroll
        for (int j = 0; j < 4; j++) acc[p][j] = 0ull;

#pragma unroll
    for (int k = 0; k < K; k++) {
        const unsigned long long* arow =
            (const unsigned long long*)(sAT + k * AST + nb);
        const unsigned long long* wrow =
            (const unsigned long long*)(sWd + k * RT + cb);
        unsigned long long a0 = arow[0], a1 = arow[1], a2 = arow[2], a3 = arow[3];
        unsigned long long w0 = wrow[0], w1 = wrow[1], w2 = wrow[2], w3 = wrow[3];
        FMA2(acc[0][0], a0, w0, acc[0][0]); FMA2(acc[0][1], a0, w1, acc[0][1]);
        FMA2(acc[0][2], a0, w2, acc[0][2]); FMA2(acc[0][3], a0, w3, acc[0][3]);
        FMA2(acc[1][0], a1, w0, acc[1][0]); FMA2(acc[1][1], a1, w1, acc[1][1]);
        FMA2(acc[1][2], a1, w2, acc[1][2]); FMA2(acc[1][3], a1, w3, acc[1][3]);
        FMA2(acc[2][0], a2, w0, acc[2][0]); FMA2(acc[2][1], a2, w1, acc[2][1]);
        FMA2(acc[2][2], a2, w2, acc[2][2]); FMA2(acc[2][3], a2, w3, acc[2][3]);
        FMA2(acc[3][0], a3, w0, acc[3][0]); FMA2(acc[3][1], a3, w1, acc[3][1]);
        FMA2(acc[3][2], a3, w2, acc[3][2]); FMA2(acc[3][3], a3, w3, acc[3][3]);
    }

    float bv[4] = {0.f, 0.f, 0.f, 0.f};
    if (bias) {
#pragma unroll
        for (int j = 0; j < 4; j++) bv[j] = bias[r0 + cb + j];
    }
#pragma unroll
    for (int p = 0; p < 4; p++) {
        float lo[4], hi[4];
#pragma unroll
        for (int j = 0; j < 4; j++) unpack2(acc[p][j], lo[j], hi[j]);
        int nA = n0 + nb + 2 * p;
        if (nA < N) {
            float4 o = make_float4(lo[0] + bv[0], lo[1] + bv[1], lo[2] + bv[2], lo[3] + bv[3]);
            if (act) { o.x = eluf_(o.x); o.y = eluf_(o.y); o.z = eluf_(o.z); o.w = eluf_(o.w); }
            *(float4*)&Y[(size_t)nA * R + r0 + cb] = o;
        }
        if (nA + 1 < N) {
            float4 o = make_float4(hi[0] + bv[0], hi[1] + bv[1], hi[2] + bv[2], hi[3] + bv[3]);
            if (act) { o.x = eluf_(o.x); o.y = eluf_(o.y); o.z = eluf_(o.z); o.w = eluf_(o.w); }
            *(float4*)&Y[(size_t)(nA + 1) * R + r0 + cb] = o;
        }
    }
}

// ---------------- CSR gather-max ----------------
template <int C>
__global__ void k_gather(const float* __restrict__ m, const int* __restrict__ rowptr,
                         const int* __restrict__ esrc, const float* __restrict__ ews,
                         float* __restrict__ agg) {
    const int NPB = 256 / C;
    int c = threadIdx.x;
    int n = blockIdx.x * NPB + threadIdx.y;
    if (n >= N_NODES) return;
    int beg = rowptr[n], end = rowptr[n + 1];
    float acc0 = -INFINITY, acc1 = -INFINITY;
    int e = beg;
    for (; e + 1 < end; e += 2) {
        int   s0 = esrc[e],     s1 = esrc[e + 1];
        float w0 = ews[e],      w1 = ews[e + 1];
        acc0 = fmaxf(acc0, m[(size_t)s0 * C + c] * w0);
        acc1 = fmaxf(acc1, m[(size_t)s1 * C + c] * w1);
    }
    if (e < end) acc0 = fmaxf(acc0, m[(size_t)esrc[e] * C + c] * ews[e]);
    float acc = fmaxf(acc0, acc1);
    agg[(size_t)n * C + c] = isfinite(acc) ? acc : 0.f;
}

// ---------------- GRU elementwise combine ----------------
template <int C>
__global__ void k_gru_comb(const float* __restrict__ gi, const float* __restrict__ gh,
                           float* __restrict__ h) {
    int i = blockIdx.x * blockDim.x + threadIdx.x;
    if (i >= N_NODES * C) return;
    int n = i / C, c = i - n * C;
    const float* gin = gi + (size_t)n * 3 * C;
    const float* ghn = gh + (size_t)n * 3 * C;
    float r  = sigmoidf_(gin[c]         + ghn[c]);
    float z  = sigmoidf_(gin[C + c]     + ghn[C + c]);
    float nn = tanhf    (gin[2 * C + c] + r * ghn[2 * C + c]);
    float hv = h[i];
    h[i] = (1.f - z) * nn + z * hv;
}

// ---------------- fc2 + log_softmax ----------------
__global__ void k_fc2_lsm(const float* __restrict__ X, const float* __restrict__ Wt,
                          const float* __restrict__ b, float* __restrict__ out) {
    int gt   = blockIdx.x * blockDim.x + threadIdx.x;
    int node = gt >> 5, lane = gt & 31;
    if (node >= N_NODES) return;
    const float* xr = X + (size_t)node * 128;
    float acc[10];
#pragma unroll
    for (int j = 0; j < 10; j++) acc[j] = 0.f;
    for (int k = lane; k < 128; k += 32) {
        float xv = xr[k];
        const float* w = Wt + k * 10;
#pragma unroll
        for (int j = 0; j < 10; j++) acc[j] = fmaf(xv, w[j], acc[j]);
    }
#pragma unroll
    for (int j = 0; j < 10; j++)
        for (int off = 16; off; off >>= 1) acc[j] += __shfl_xor_sync(0xffffffffu, acc[j], off);
    float mx = -INFINITY;
#pragma unroll
    for (int j = 0; j < 10; j++) { acc[j] += b[j]; mx = fmaxf(mx, acc[j]); }
    float se = 0.f;
#pragma unroll
    for (int j = 0; j < 10; j++) se += expf(acc[j] - mx);
    float lse = mx + logf(se);
    if (lane < 10) out[(size_t)node * 10 + lane] = acc[lane] - lse;
}

// ---------------- launch ----------------
static inline int gdiv(int n) { return (n + 255) / 256; }

extern "C" void kernel_launch(void* const* d_in, const int* in_sizes, int n_in,
                              void* d_out, int out_size) {
    const float* x    = (const float*)d_in[0];
    const void*  eraw = d_in[1];
    const float* ea   = (const float*)d_in[2];
    const float* W1   = (const float*)d_in[3];
    const float* Wih1 = (const float*)d_in[4];
    const float* Whh1 = (const float*)d_in[5];
    const float* bih1 = (const float*)d_in[6];
    const float* bhh1 = (const float*)d_in[7];
    const float* W2   = (const float*)d_in[8];
    const float* Wih2 = (const float*)d_in[9];
    const float* Whh2 = (const float*)d_in[10];
    const float* bih2 = (const float*)d_in[11];
    const float* bhh2 = (const float*)d_in[12];
    const float* fc1w = (const float*)d_in[13];
    const float* fc1b = (const float*)d_in[14];
    const float* fc2w = (const float*)d_in[15];
    const float* fc2b = (const float*)d_in[16];
    float* out = (float*)d_out;

    float *hA, *hB, *m, *agg, *gi, *gh, *hid;
    float *WT1ih, *WT1hh, *WT2ih, *WT2hh, *fc1T, *fc2T, *ews;
    int *ei32, *deg, *rowptr, *cursor, *esrc;
    cudaGetSymbolAddress((void**)&hA,    g_hA);
    cudaGetSymbolAddress((void**)&hB,    g_hB);
    cudaGetSymbolAddress((void**)&m,     g_m);
    cudaGetSymbolAddress((void**)&agg,   g_agg);
    cudaGetSymbolAddress((void**)&gi,    g_gi);
    cudaGetSymbolAddress((void**)&gh,    g_gh);
    cudaGetSymbolAddress((void**)&hid,   g_hid);
    cudaGetSymbolAddress((void**)&WT1ih, g_WT1ih);
    cudaGetSymbolAddress((void**)&WT1hh, g_WT1hh);
    cudaGetSymbolAddress((void**)&WT2ih, g_WT2ih);
    cudaGetSymbolAddress((void**)&WT2hh, g_WT2hh);
    cudaGetSymbolAddress((void**)&fc1T,  g_fc1T);
    cudaGetSymbolAddress((void**)&fc2T,  g_fc2T);
    cudaGetSymbolAddress((void**)&ei32,  g_ei32);
    cudaGetSymbolAddress((void**)&deg,   g_deg);
    cudaGetSymbolAddress((void**)&rowptr,g_rowptr);
    cudaGetSymbolAddress((void**)&cursor,g_cursor);
    cudaGetSymbolAddress((void**)&esrc,  g_esrc);
    cudaGetSymbolAddress((void**)&ews,   g_ews);

    const int TB = 256;

    // dynamic smem opt-in (>48KB) for the f32x2 gemms
    const int SM64 = 64 * 130 * 4 + 64 * 64 * 8;   // 66048 B
    const int SM32 = 32 * 130 * 4 + 32 * 32 * 8;   // 24832 B
    cudaFuncSetAttribute(k_gemm2<64, 64, 128>, cudaFuncAttributeMaxDynamicSharedMemorySize, SM64);
    cudaFuncSetAttribute(k_gemm2<32, 32, 128>, cudaFuncAttributeMaxDynamicSharedMemorySize, SM32);

    const int GN = (N_NODES + 127) / 128;   // 782

    // edge indices -> int32, CSR by destination
    k_sniff<<<1, 1024>>>(eraw);
    k_convert<<<gdiv(2 * N_EDGES), TB>>>(eraw, ei32);
    k_zero_i<<<gdiv(N_NODES), TB>>>(deg, N_NODES);
    k_count<<<gdiv(N_EDGES), TB>>>(ei32, deg);
    k_scan<<<1, 1024>>>(deg, rowptr);
    k_copy_i<<<gdiv(N_NODES), TB>>>(rowptr, cursor, N_NODES);
    k_place<<<gdiv(N_EDGES), TB>>>(ei32, ea, cursor, esrc, ews);

    // weight transposes (k-major)
    k_transpose<<<gdiv(96 * 32),  TB>>>(Wih1, WT1ih, 96,  32);
    k_transpose<<<gdiv(96 * 32),  TB>>>(Whh1, WT1hh, 96,  32);
    k_transpose<<<gdiv(192 * 64), TB>>>(Wih2, WT2ih, 192, 64);
    k_transpose<<<gdiv(192 * 64), TB>>>(Whh2, WT2hh, 192, 64);
    k_transpose<<<gdiv(128 * 64), TB>>>(fc1w, fc1T,  128, 64);
    k_transpose<<<gdiv(10 * 128), TB>>>(fc2w, fc2T,  10,  128);

    // ---- layer 1 (C=32) ----
    k_init_h<<<gdiv(N_NODES * 32), TB>>>(x, hA);
    for (int i = 0; i < 3; i++) {
        k_gemm2<32, 32, 128><<<dim3(GN, 1), 128, SM32>>>(hA, W1 + i * 32 * 32, nullptr, m, N_NODES, 32, 0, 0);
        { dim3 blk(32, 8); k_gather<32><<<(N_NODES + 7) / 8, blk>>>(m, rowptr, esrc, ews, agg); }
        k_gemm2<32, 32, 128><<<dim3(GN, 3), 128, SM32>>>(agg, WT1ih, bih1, gi, N_NODES, 96, 0, 0);
        k_gemm2<32, 32, 128><<<dim3(GN, 3), 128, SM32>>>(hA,  WT1hh, bhh1, gh, N_NODES, 96, 0, 0);
        k_gru_comb<32><<<gdiv(N_NODES * 32), TB>>>(gi, gh, hA);
    }

    k_pad_elu<<<gdiv(N_NODES * 64), TB>>>(hA, hB);

    // ---- layer 2 (C=64) ----
    for (int i = 0; i < 3; i++) {
        k_gemm2<64, 64, 128><<<dim3(GN, 1), 256, SM64>>>(hB, W2 + i * 64 * 64, nullptr, m, N_NODES, 64, 0, 0);
        { dim3 blk(64, 4); k_gather<64><<<(N_NODES + 3) / 4, blk>>>(m, rowptr, esrc, ews, agg); }
        k_gemm2<64, 64, 128><<<dim3(GN, 3), 256, SM64>>>(agg, WT2ih, bih2, gi, N_NODES, 192, 0, 0);
        k_gemm2<64, 64, 128><<<dim3(GN, 3), 256, SM64>>>(hB,  WT2hh, bhh2, gh, N_NODES, 192, 0, 0);
        k_gru_comb<64><<<gdiv(N_NODES * 64), TB>>>(gi, gh, hB);
    }

    // ---- head: fc1 (elu fused on input and output), fc2 + log_softmax ----
    k_gemm2<64, 64, 128><<<dim3(GN, 2), 256, SM64>>>(hB, fc1T, fc1b, hid, N_NODES, 128, 1, 1);
    k_fc2_lsm<<<gdiv(N_NODES * 32), TB>>>(hid, fc2T, fc2b, out);
}

// round 5
// speedup vs baseline: 1.4314x; 1.4314x over previous
#include <cuda_runtime.h>
#include <math.h>

#define N_NODES 100000
#define N_EDGES 1600000

// ---------------- device scratch ----------------
__device__ float g_hA [N_NODES * 32];
__device__ float g_hB [N_NODES * 64];
__device__ float g_m  [N_NODES * 64];
__device__ float g_agg[N_NODES * 64];
__device__ float g_hid[N_NODES * 128];
__device__ float g_WT1ih[32 * 96];
__device__ float g_WT1hh[32 * 96];
__device__ float g_WT2ih[64 * 192];
__device__ float g_WT2hh[64 * 192];
__device__ float g_fc1T[64 * 128];
__device__ float g_fc2T[128 * 10];
__device__ int   g_ei32[2 * N_EDGES];
__device__ int   g_deg [N_NODES];
__device__ int   g_rowptr[N_NODES + 1];
__device__ int   g_cursor[N_NODES];
__device__ int   g_esrc[N_EDGES];
__device__ float g_ews [N_EDGES];
__device__ int   g_is64;

// ---------------- helpers ----------------
__device__ __forceinline__ float sigmoidf_(float x) { return 1.0f / (1.0f + expf(-x)); }
__device__ __forceinline__ float eluf_(float x)     { return x > 0.f ? x : expm1f(x); }

// ---------------- edge-index dtype sniff + normalize ----------------
__global__ void k_sniff(const void* __restrict__ p) {
    __shared__ int s_bad;
    if (threadIdx.x == 0) s_bad = 0;
    __syncthreads();
    long long v = ((const long long*)p)[threadIdx.x];
    if (v < 0 || v >= N_NODES) atomicAdd(&s_bad, 1);
    __syncthreads();
    if (threadIdx.x == 0) g_is64 = (s_bad < 512) ? 1 : 0;
}

__global__ void k_convert(const void* __restrict__ p, int* __restrict__ out) {
    int i = blockIdx.x * blockDim.x + threadIdx.x;
    if (i >= 2 * N_EDGES) return;
    out[i] = g_is64 ? (int)((const long long*)p)[i] : ((const int*)p)[i];
}

// ---------------- CSR build ----------------
__global__ void k_zero_i(int* __restrict__ p, int n) {
    int i = blockIdx.x * blockDim.x + threadIdx.x;
    if (i < n) p[i] = 0;
}

__global__ void k_count(const int* __restrict__ ei, int* __restrict__ deg) {
    int e = blockIdx.x * blockDim.x + threadIdx.x;
    if (e >= N_EDGES) return;
    int d = ei[N_EDGES + e];
    if ((unsigned)d < N_NODES) atomicAdd(&deg[d], 1);
}

// shuffle-based exclusive scan, 1024 threads, 3 syncs per 1024-chunk
__global__ void k_scan(const int* __restrict__ deg, int* __restrict__ rowptr) {
    __shared__ int warp_sums[32];
    __shared__ int s_off;
    int tid = threadIdx.x, lane = tid & 31, wid = tid >> 5;
    if (tid == 0) s_off = 0;
    __syncthreads();
    for (int base = 0; base < N_NODES; base += 1024) {
        int i = base + tid;
        int v = (i < N_NODES) ? deg[i] : 0;
        int x = v;
#pragma unroll
        for (int d = 1; d < 32; d <<= 1) {
            int t = __shfl_up_sync(0xffffffffu, x, d);
            if (lane >= d) x += t;
        }
        if (lane == 31) warp_sums[wid] = x;
        __syncthreads();
        if (wid == 0) {
            int s = warp_sums[lane];
#pragma unroll
            for (int d = 1; d < 32; d <<= 1) {
                int t = __shfl_up_sync(0xffffffffu, s, d);
                if (lane >= d) s += t;
            }
            warp_sums[lane] = s;
        }
        __syncthreads();
        int pre = (wid > 0) ? warp_sums[wid - 1] : 0;
        if (i < N_NODES) rowptr[i] = s_off + pre + x - v;
        int total = warp_sums[31];
        __syncthreads();
        if (tid == 0) s_off += total;
    }
    __syncthreads();
    if (tid == 0) rowptr[N_NODES] = s_off;
}

__global__ void k_copy_i(const int* __restrict__ a, int* __restrict__ b, int n) {
    int i = blockIdx.x * blockDim.x + threadIdx.x;
    if (i < n) b[i] = a[i];
}

__global__ void k_place(const int* __restrict__ ei, const float* __restrict__ ea,
                        int* __restrict__ cursor, int* __restrict__ esrc,
                        float* __restrict__ ews) {
    int e = blockIdx.x * blockDim.x + threadIdx.x;
    if (e >= N_EDGES) return;
    int s = ei[e];
    int d = ei[N_EDGES + e];
    if ((unsigned)s >= N_NODES || (unsigned)d >= N_NODES) return;
    int pos = atomicAdd(&cursor[d], 1);
    esrc[pos] = s;
    ews[pos]  = ea[e];
}

// ---------------- init / elementwise ----------------
__global__ void k_transpose(const float* __restrict__ W, float* __restrict__ WT, int R, int K) {
    int idx = blockIdx.x * blockDim.x + threadIdx.x;
    if (idx < R * K) { int r = idx / K, k = idx - r * K; WT[k * R + r] = W[idx]; }
}

__global__ void k_init_h(const float* __restrict__ x, float* __restrict__ h) {
    int i = blockIdx.x * blockDim.x + threadIdx.x;
    if (i < N_NODES * 32) {
        int n = i >> 5, c = i & 31;
        h[i] = (c < 16) ? x[n * 16 + c] : 0.f;
    }
}

__global__ void k_pad_elu(const float* __restrict__ src, float* __restrict__ dst) {
    int i = blockIdx.x * blockDim.x + threadIdx.x;
    if (i < N_NODES * 64) {
        int n = i >> 6, c = i & 63;
        dst[i] = (c < 32) ? eluf_(src[n * 32 + c]) : 0.f;
    }
}

// ---------------- tiled GEMM (R3-proven): Y = act(X[opt elu] @ WT + bias) ----------------
template <int K, int RT>
__global__ void k_gemm_t(const float* __restrict__ X, const float* __restrict__ WT,
                         const float* __restrict__ bias, float* __restrict__ Y,
                         int N, int R, int act, int in_act) {
    const int NT = 64;
    __shared__ float sX[NT][K];
    __shared__ float sW[K][RT];
    int n0 = blockIdx.x * NT;
    int r0 = blockIdx.y * RT;
    int tid = threadIdx.x;

    for (int i = tid; i < NT * K; i += blockDim.x) {
        int n = i / K, k = i - n * K;
        int nn = n0 + n;
        float v = (nn < N) ? X[(size_t)nn * K + k] : 0.f;
        if (in_act) v = eluf_(v);
        sX[n][k] = v;
    }
    for (int i = tid; i < K * RT; i += blockDim.x) {
        int k = i / RT, r = i - k * RT;
        sW[k][r] = WT[(size_t)k * R + r0 + r];
    }
    __syncthreads();

    int tc = tid % (RT / 4);
    int tn = tid / (RT / 4);
    float acc[4][4];
#pragma unroll
    for (int i = 0; i < 4; i++)
#pragma unroll
        for (int j = 0; j < 4; j++) acc[i][j] = 0.f;

#pragma unroll
    for (int k = 0; k < K; k++) {
        float a0 = sX[tn * 4 + 0][k];
        float a1 = sX[tn * 4 + 1][k];
        float a2 = sX[tn * 4 + 2][k];
        float a3 = sX[tn * 4 + 3][k];
        float4 b = *(const float4*)&sW[k][tc * 4];
        acc[0][0] = fmaf(a0, b.x, acc[0][0]); acc[0][1] = fmaf(a0, b.y, acc[0][1]);
        acc[0][2] = fmaf(a0, b.z, acc[0][2]); acc[0][3] = fmaf(a0, b.w, acc[0][3]);
        acc[1][0] = fmaf(a1, b.x, acc[1][0]); acc[1][1] = fmaf(a1, b.y, acc[1][1]);
        acc[1][2] = fmaf(a1, b.z, acc[1][2]); acc[1][3] = fmaf(a1, b.w, acc[1][3]);
        acc[2][0] = fmaf(a2, b.x, acc[2][0]); acc[2][1] = fmaf(a2, b.y, acc[2][1]);
        acc[2][2] = fmaf(a2, b.z, acc[2][2]); acc[2][3] = fmaf(a2, b.w, acc[2][3]);
        acc[3][0] = fmaf(a3, b.x, acc[3][0]); acc[3][1] = fmaf(a3, b.y, acc[3][1]);
        acc[3][2] = fmaf(a3, b.z, acc[3][2]); acc[3][3] = fmaf(a3, b.w, acc[3][3]);
    }

    float bv[4] = {0.f, 0.f, 0.f, 0.f};
    if (bias) {
#pragma unroll
        for (int j = 0; j < 4; j++) bv[j] = bias[r0 + tc * 4 + j];
    }
#pragma unroll
    for (int i = 0; i < 4; i++) {
        int nn = n0 + tn * 4 + i;
        if (nn >= N) continue;
        float4 o;
        o.x = acc[i][0] + bv[0]; o.y = acc[i][1] + bv[1];
        o.z = acc[i][2] + bv[2]; o.w = acc[i][3] + bv[3];
        if (act) { o.x = eluf_(o.x); o.y = eluf_(o.y); o.z = eluf_(o.z); o.w = eluf_(o.w); }
        *(float4*)&Y[(size_t)nn * R + r0 + tc * 4] = o;
    }
}

// ---------------- fused GRU cell ----------------
// Per block: 64 nodes. Each thread: 2 nodes x 4 channels, all 6 gate partials
// accumulated in registers; sigmoid/tanh combine in-register; writes h directly.
// WiT/WhT are k-major [C][3C]. No gi/gh global buffers.
template <int C>
__global__ void __launch_bounds__((C / 4) * 32)
k_gru_fused(const float* __restrict__ agg, float* __restrict__ h,
            const float* __restrict__ WiT, const float* __restrict__ WhT,
            const float* __restrict__ bih, const float* __restrict__ bhh, int N) {
    const int KC = 16;
    const int NT = 64;
    const int NTH = (C / 4) * 32;
    __shared__ float sA[NT][KC];
    __shared__ float sH[NT][KC];
    __shared__ float sWi[KC][3 * C];
    __shared__ float sWh[KC][3 * C];

    int tid = threadIdx.x;
    int tc = tid % (C / 4);
    int tn = tid / (C / 4);        // 0..31
    int n0 = blockIdx.x * NT;
    int cb = 4 * tc;

    float ir[2][4], iz[2][4], in_[2][4], hr[2][4], hz[2][4], hn[2][4];
#pragma unroll
    for (int p = 0; p < 2; p++)
#pragma unroll
        for (int j = 0; j < 4; j++) {
            ir[p][j] = iz[p][j] = in_[p][j] = 0.f;
            hr[p][j] = hz[p][j] = hn[p][j] = 0.f;
        }

    for (int kc = 0; kc < C; kc += KC) {
        for (int i = tid; i < NT * KC; i += NTH) {
            int n = i / KC, kk = i - n * KC;
            int nn = n0 + n;
            sA[n][kk] = (nn < N) ? agg[(size_t)nn * C + kc + kk] : 0.f;
            sH[n][kk] = (nn < N) ? h[(size_t)nn * C + kc + kk] : 0.f;
        }
        for (int i = tid; i < KC * 3 * C; i += NTH) {
            int k = i / (3 * C), c = i - k * 3 * C;
            sWi[k][c] = WiT[(size_t)(kc + k) * 3 * C + c];
            sWh[k][c] = WhT[(size_t)(kc + k) * 3 * C + c];
        }
        __syncthreads();

#pragma unroll
        for (int kk = 0; kk < KC; kk++) {
            float a0 = sA[2 * tn][kk],     a1 = sA[2 * tn + 1][kk];
            float h0 = sH[2 * tn][kk],     h1 = sH[2 * tn + 1][kk];
            float wir[4], wiz[4], win[4], whr[4], whz[4], whn[4];
            *(float4*)wir = *(const float4*)&sWi[kk][0 * C + cb];
            *(float4*)wiz = *(const float4*)&sWi[kk][1 * C + cb];
            *(float4*)win = *(const float4*)&sWi[kk][2 * C + cb];
            *(float4*)whr = *(const float4*)&sWh[kk][0 * C + cb];
            *(float4*)whz = *(const float4*)&sWh[kk][1 * C + cb];
            *(float4*)whn = *(const float4*)&sWh[kk][2 * C + cb];
#pragma unroll
            for (int j = 0; j < 4; j++) {
                ir[0][j]  = fmaf(a0, wir[j], ir[0][j]);  ir[1][j]  = fmaf(a1, wir[j], ir[1][j]);
                iz[0][j]  = fmaf(a0, wiz[j], iz[0][j]);  iz[1][j]  = fmaf(a1, wiz[j], iz[1][j]);
                in_[0][j] = fmaf(a0, win[j], in_[0][j]); in_[1][j] = fmaf(a1, win[j], in_[1][j]);
                hr[0][j]  = fmaf(h0, whr[j], hr[0][j]);  hr[1][j]  = fmaf(h1, whr[j], hr[1][j]);
                hz[0][j]  = fmaf(h0, whz[j], hz[0][j]);  hz[1][j]  = fmaf(h1, whz[j], hz[1][j]);
                hn[0][j]  = fmaf(h0, whn[j], hn[0][j]);  hn[1][j]  = fmaf(h1, whn[j], hn[1][j]);
            }
        }
        __syncthreads();
    }

    float bir[4], biz[4], bin[4], bhr[4], bhz[4], bhn[4];
#pragma unroll
    for (int j = 0; j < 4; j++) {
        bir[j] = bih[cb + j]; biz[j] = bih[C + cb + j]; bin[j] = bih[2 * C + cb + j];
        bhr[j] = bhh[cb + j]; bhz[j] = bhh[C + cb + j]; bhn[j] = bhh[2 * C + cb + j];
    }
#pragma unroll
    for (int p = 0; p < 2; p++) {
        int nn = n0 + 2 * tn + p;
        if (nn >= N) continue;
        float ho[4];
        *(float4*)ho = *(const float4*)&h[(size_t)nn * C + cb];
        float o[4];
#pragma unroll
        for (int j = 0; j < 4; j++) {
            float r  = sigmoidf_(ir[p][j] + bir[j] + hr[p][j] + bhr[j]);
            float z  = sigmoidf_(iz[p][j] + biz[j] + hz[p][j] + bhz[j]);
            float nv = tanhf(in_[p][j] + bin[j] + r * (hn[p][j] + bhn[j]));
            o[j] = (1.f - z) * nv + z * ho[j];
        }
        *(float4*)&h[(size_t)nn * C + cb] = *(float4*)o;
    }
}

// ---------------- CSR gather-max ----------------
template <int C>
__global__ void k_gather(const float* __restrict__ m, const int* __restrict__ rowptr,
                         const int* __restrict__ esrc, const float* __restrict__ ews,
                         float* __restrict__ agg) {
    const int NPB = 256 / C;
    int c = threadIdx.x;
    int n = blockIdx.x * NPB + threadIdx.y;
    if (n >= N_NODES) return;
    int beg = rowptr[n], end = rowptr[n + 1];
    float acc0 = -INFINITY, acc1 = -INFINITY;
    int e = beg;
    for (; e + 1 < end; e += 2) {
        int   s0 = esrc[e], s1 = esrc[e + 1];
        float w0 = ews[e],  w1 = ews[e + 1];
        acc0 = fmaxf(acc0, m[(size_t)s0 * C + c] * w0);
        acc1 = fmaxf(acc1, m[(size_t)s1 * C + c] * w1);
    }
    if (e < end) acc0 = fmaxf(acc0, m[(size_t)esrc[e] * C + c] * ews[e]);
    float acc = fmaxf(acc0, acc1);
    agg[(size_t)n * C + c] = isfinite(acc) ? acc : 0.f;
}

// ---------------- fc2 + log_softmax ----------------
__global__ void k_fc2_lsm(const float* __restrict__ X, const float* __restrict__ Wt,
                          const float* __restrict__ b, float* __restrict__ out) {
    int gt   = blockIdx.x * blockDim.x + threadIdx.x;
    int node = gt >> 5, lane = gt & 31;
    if (node >= N_NODES) return;
    const float* xr = X + (size_t)node * 128;
    float acc[10];
#pragma unroll
    for (int j = 0; j < 10; j++) acc[j] = 0.f;
    for (int k = lane; k < 128; k += 32) {
        float xv = xr[k];
        const float* w = Wt + k * 10;
#pragma unroll
        for (int j = 0; j < 10; j++) acc[j] = fmaf(xv, w[j], acc[j]);
    }
#pragma unroll
    for (int j = 0; j < 10; j++)
        for (int off = 16; off; off >>= 1) acc[j] += __shfl_xor_sync(0xffffffffu, acc[j], off);
    float mx = -INFINITY;
#pragma unroll
    for (int j = 0; j < 10; j++) { acc[j] += b[j]; mx = fmaxf(mx, acc[j]); }
    float se = 0.f;
#pragma unroll
    for (int j = 0; j < 10; j++) se += expf(acc[j] - mx);
    float lse = mx + logf(se);
    if (lane < 10) out[(size_t)node * 10 + lane] = acc[lane] - lse;
}

// ---------------- launch ----------------
static inline int gdiv(int n) { return (n + 255) / 256; }

extern "C" void kernel_launch(void* const* d_in, const int* in_sizes, int n_in,
                              void* d_out, int out_size) {
    const float* x    = (const float*)d_in[0];
    const void*  eraw = d_in[1];
    const float* ea   = (const float*)d_in[2];
    const float* W1   = (const float*)d_in[3];
    const float* Wih1 = (const float*)d_in[4];
    const float* Whh1 = (const float*)d_in[5];
    const float* bih1 = (const float*)d_in[6];
    const float* bhh1 = (const float*)d_in[7];
    const float* W2   = (const float*)d_in[8];
    const float* Wih2 = (const float*)d_in[9];
    const float* Whh2 = (const float*)d_in[10];
    const float* bih2 = (const float*)d_in[11];
    const float* bhh2 = (const float*)d_in[12];
    const float* fc1w = (const float*)d_in[13];
    const float* fc1b = (const float*)d_in[14];
    const float* fc2w = (const float*)d_in[15];
    const float* fc2b = (const float*)d_in[16];
    float* out = (float*)d_out;

    float *hA, *hB, *m, *agg, *hid;
    float *WT1ih, *WT1hh, *WT2ih, *WT2hh, *fc1T, *fc2T, *ews;
    int *ei32, *deg, *rowptr, *cursor, *esrc;
    cudaGetSymbolAddress((void**)&hA,    g_hA);
    cudaGetSymbolAddress((void**)&hB,    g_hB);
    cudaGetSymbolAddress((void**)&m,     g_m);
    cudaGetSymbolAddress((void**)&agg,   g_agg);
    cudaGetSymbolAddress((void**)&hid,   g_hid);
    cudaGetSymbolAddress((void**)&WT1ih, g_WT1ih);
    cudaGetSymbolAddress((void**)&WT1hh, g_WT1hh);
    cudaGetSymbolAddress((void**)&WT2ih, g_WT2ih);
    cudaGetSymbolAddress((void**)&WT2hh, g_WT2hh);
    cudaGetSymbolAddress((void**)&fc1T,  g_fc1T);
    cudaGetSymbolAddress((void**)&fc2T,  g_fc2T);
    cudaGetSymbolAddress((void**)&ei32,  g_ei32);
    cudaGetSymbolAddress((void**)&deg,   g_deg);
    cudaGetSymbolAddress((void**)&rowptr,g_rowptr);
    cudaGetSymbolAddress((void**)&cursor,g_cursor);
    cudaGetSymbolAddress((void**)&esrc,  g_esrc);
    cudaGetSymbolAddress((void**)&ews,   g_ews);

    const int TB = 256;
    const int GN = (N_NODES + 63) / 64;   // 1563

    // edge indices -> int32, CSR by destination
    k_sniff<<<1, 1024>>>(eraw);
    k_convert<<<gdiv(2 * N_EDGES), TB>>>(eraw, ei32);
    k_zero_i<<<gdiv(N_NODES), TB>>>(deg, N_NODES);
    k_count<<<gdiv(N_EDGES), TB>>>(ei32, deg);
    k_scan<<<1, 1024>>>(deg, rowptr);
    k_copy_i<<<gdiv(N_NODES), TB>>>(rowptr, cursor, N_NODES);
    k_place<<<gdiv(N_EDGES), TB>>>(ei32, ea, cursor, esrc, ews);

    // weight transposes (k-major)
    k_transpose<<<gdiv(96 * 32),  TB>>>(Wih1, WT1ih, 96,  32);
    k_transpose<<<gdiv(96 * 32),  TB>>>(Whh1, WT1hh, 96,  32);
    k_transpose<<<gdiv(192 * 64), TB>>>(Wih2, WT2ih, 192, 64);
    k_transpose<<<gdiv(192 * 64), TB>>>(Whh2, WT2hh, 192, 64);
    k_transpose<<<gdiv(128 * 64), TB>>>(fc1w, fc1T,  128, 64);
    k_transpose<<<gdiv(10 * 128), TB>>>(fc2w, fc2T,  10,  128);

    // ---- layer 1 (C=32) ----
    k_init_h<<<gdiv(N_NODES * 32), TB>>>(x, hA);
    for (int i = 0; i < 3; i++) {
        k_gemm_t<32, 32><<<dim3(GN, 1), 128>>>(hA, W1 + i * 32 * 32, nullptr, m, N_NODES, 32, 0, 0);
        { dim3 blk(32, 8); k_gather<32><<<(N_NODES + 7) / 8, blk>>>(m, rowptr, esrc, ews, agg); }
        k_gru_fused<32><<<GN, (32 / 4) * 32>>>(agg, hA, WT1ih, WT1hh, bih1, bhh1, N_NODES);
    }

    k_pad_elu<<<gdiv(N_NODES * 64), TB>>>(hA, hB);

    // ---- layer 2 (C=64) ----
    for (int i = 0; i < 3; i++) {
        k_gemm_t<64, 64><<<dim3(GN, 1), 256>>>(hB, W2 + i * 64 * 64, nullptr, m, N_NODES, 64, 0, 0);
        { dim3 blk(64, 4); k_gather<64><<<(N_NODES + 3) / 4, blk>>>(m, rowptr, esrc, ews, agg); }
        k_gru_fused<64><<<GN, (64 / 4) * 32>>>(agg, hB, WT2ih, WT2hh, bih2, bhh2, N_NODES);
    }

    // ---- head: fc1 (elu on input and output fused), fc2 + log_softmax ----
    k_gemm_t<64, 64><<<dim3(GN, 2), 256>>>(hB, fc1T, fc1b, hid, N_NODES, 128, 1, 1);
    k_fc2_lsm<<<gdiv(N_NODES * 32), TB>>>(hid, fc2T, fc2b, out);
}

// round 7
// speedup vs baseline: 1.4579x; 1.0186x over previous
#include <cuda_runtime.h>
#include <cuda_bf16.h>
#include <mma.h>
#include <math.h>
#include <stdint.h>

#define N_NODES 100000
#define N_EDGES 1600000

// ---------------- device scratch ----------------
__device__ float g_hA [N_NODES * 32];
__device__ float g_hB [N_NODES * 64];
__device__ float g_m  [N_NODES * 64];
__device__ float g_agg[N_NODES * 64];
__device__ float g_gi [N_NODES * 192];
__device__ float g_gh [N_NODES * 192];
__device__ float g_hid[N_NODES * 128];
__device__ float g_fc2T[128 * 10];
__device__ unsigned char g_wimg[262144];   // padded bf16 hi/lo weight images
__device__ int   g_ei32[2 * N_EDGES];
__device__ int   g_deg [N_NODES];
__device__ int   g_rowptr[N_NODES + 1];
__device__ int   g_cursor[N_NODES];
__device__ int   g_esrc[N_EDGES];
__device__ float g_ews [N_EDGES];
__device__ int   g_is64;

// weight image byte offsets: each image = R*KP*2 bytes hi, then R*KP*2 bytes lo
#define OFF_W1   0        // 3 x 5120   (R=32,KP=40)
#define OFF_WIH1 15360    // 15360      (R=96,KP=40)
#define OFF_WHH1 30720
#define OFF_W2   46080    // 3 x 18432  (R=64,KP=72)
#define OFF_WIH2 101376   // 55296      (R=192,KP=72)
#define OFF_WHH2 156672
#define OFF_FC1  211968   // 36864      (R=128,KP=72)

// ---------------- helpers ----------------
__device__ __forceinline__ float sigmoidf_(float x) { return 1.0f / (1.0f + expf(-x)); }
__device__ __forceinline__ float eluf_(float x)     { return x > 0.f ? x : expm1f(x); }

// ---------------- preprocessing ----------------
__global__ void k_sniff(const void* __restrict__ p) {
    __shared__ int s_bad;
    if (threadIdx.x == 0) s_bad = 0;
    __syncthreads();
    long long v = ((const long long*)p)[threadIdx.x];
    if (v < 0 || v >= N_NODES) atomicAdd(&s_bad, 1);
    __syncthreads();
    if (threadIdx.x == 0) g_is64 = (s_bad < 512) ? 1 : 0;
}

__global__ void k_convert(const void* __restrict__ p, int* __restrict__ out) {
    int i = blockIdx.x * blockDim.x + threadIdx.x;
    if (i >= 2 * N_EDGES) return;
    out[i] = g_is64 ? (int)((const long long*)p)[i] : ((const int*)p)[i];
}

__global__ void k_zero_i(int* __restrict__ p, int n) {
    int i = blockIdx.x * blockDim.x + threadIdx.x;
    if (i < n) p[i] = 0;
}

__global__ void k_count(const int* __restrict__ ei, int* __restrict__ deg) {
    int e = blockIdx.x * blockDim.x + threadIdx.x;
    if (e >= N_EDGES) return;
    int d = ei[N_EDGES + e];
    if ((unsigned)d < N_NODES) atomicAdd(&deg[d], 1);
}

__global__ void k_scan(const int* __restrict__ deg, int* __restrict__ rowptr) {
    __shared__ int warp_sums[32];
    __shared__ int s_off;
    int tid = threadIdx.x, lane = tid & 31, wid = tid >> 5;
    if (tid == 0) s_off = 0;
    __syncthreads();
    for (int base = 0; base < N_NODES; base += 1024) {
        int i = base + tid;
        int v = (i < N_NODES) ? deg[i] : 0;
        int x = v;
#pragma unroll
        for (int d = 1; d < 32; d <<= 1) {
            int t = __shfl_up_sync(0xffffffffu, x, d);
            if (lane >= d) x += t;
        }
        if (lane == 31) warp_sums[wid] = x;
        __syncthreads();
        if (wid == 0) {
            int s = warp_sums[lane];
#pragma unroll
            for (int d = 1; d < 32; d <<= 1) {
                int t = __shfl_up_sync(0xffffffffu, s, d);
                if (lane >= d) s += t;
            }
            warp_sums[lane] = s;
        }
        __syncthreads();
        int pre = (wid > 0) ? warp_sums[wid - 1] : 0;
        if (i < N_NODES) rowptr[i] = s_off + pre + x - v;
        int total = warp_sums[31];
        __syncthreads();
        if (tid == 0) s_off += total;
    }
    __syncthreads();
    if (tid == 0) rowptr[N_NODES] = s_off;
}

__global__ void k_copy_i(const int* __restrict__ a, int* __restrict__ b, int n) {
    int i = blockIdx.x * blockDim.x + threadIdx.x;
    if (i < n) b[i] = a[i];
}

__global__ void k_place(const int* __restrict__ ei, const float* __restrict__ ea,
                        int* __restrict__ cursor, int* __restrict__ esrc,
                        float* __restrict__ ews) {
    int e = blockIdx.x * blockDim.x + threadIdx.x;
    if (e >= N_EDGES) return;
    int s = ei[e];
    int d = ei[N_EDGES + e];
    if ((unsigned)s >= N_NODES || (unsigned)d >= N_NODES) return;
    int pos = atomicAdd(&cursor[d], 1);
    esrc[pos] = s;
    ews[pos]  = ea[e];
}

// weight image prep: dst = [R][KP] bf16 hi image, lo image at +R*KP elems
__global__ void k_prep_w(const float* __restrict__ src, unsigned char* __restrict__ dst,
                         int R, int K, int KP, int trans) {
    int idx = blockIdx.x * blockDim.x + threadIdx.x;
    if (idx >= R * KP) return;
    int r = idx / KP, k = idx - r * KP;
    float v = 0.f;
    if (k < K) v = trans ? src[k * R + r] : src[r * K + k];
    __nv_bfloat16 h = __float2bfloat16(v);
    __nv_bfloat16 l = __float2bfloat16(v - __bfloat162float(h));
    __nv_bfloat16* d16 = (__nv_bfloat16*)dst;
    d16[r * KP + k]          = h;
    d16[R * KP + r * KP + k] = l;
}

__global__ void k_transpose(const float* __restrict__ W, float* __restrict__ WT, int R, int K) {
    int idx = blockIdx.x * blockDim.x + threadIdx.x;
    if (idx < R * K) { int r = idx / K, k = idx - r * K; WT[k * R + r] = W[idx]; }
}

__global__ void k_init_h(const float* __restrict__ x, float* __restrict__ h) {
    int i = blockIdx.x * blockDim.x + threadIdx.x;
    if (i < N_NODES * 32) {
        int n = i >> 5, c = i & 31;
        h[i] = (c < 16) ? x[n * 16 + c] : 0.f;
    }
}

__global__ void k_pad_elu(const float* __restrict__ src, float* __restrict__ dst) {
    int i = blockIdx.x * blockDim.x + threadIdx.x;
    if (i < N_NODES * 64) {
        int n = i >> 6, c = i & 63;
        dst[i] = (c < 32) ? eluf_(src[n * 32 + c]) : 0.f;
    }
}

// ---------------- HMMA bf16x3 GEMM: Y[N x R] = act(X[N x K] @ B^T + bias) ----------------
// B image: [R][KP] bf16 hi, then lo. CTA: 128 nodes, 8 warps (16 rows each).
template <int K, int R, int ACT>
__global__ void __launch_bounds__(256)
tgemm(const float* __restrict__ X, const unsigned char* __restrict__ wimg,
      const float* __restrict__ bias, float* __restrict__ Y, int N, int in_act) {
    using namespace nvcuda;
    constexpr int KP = K + 8;
    extern __shared__ unsigned char smem[];
    __nv_bfloat16* sAh = (__nv_bfloat16*)smem;            // 128*KP
    __nv_bfloat16* sAl = sAh + 128 * KP;
    __nv_bfloat16* sBh = sAl + 128 * KP;                  // R*KP (hi), then lo contiguous
    float* sEp = (float*)smem;                            // epilogue buffer, reuses A region

    int tid = threadIdx.x, wid = tid >> 5;
    int n0 = blockIdx.x * 128;

    // stage B hi+lo (uint4 copy of padded row-major image)
    {
        const uint4* bsrc = (const uint4*)wimg;
        uint4* bdst = (uint4*)sBh;
        for (int i = tid; i < (R * KP) / 4; i += 256) bdst[i] = bsrc[i];
    }
    // stage A: fp32 -> bf16 hi/lo
    for (int i = tid; i < 128 * K; i += 256) {
        int r = i / K, k = i - r * K;
        int nn = n0 + r;
        float v = (nn < N) ? X[(size_t)nn * K + k] : 0.f;
        if (in_act) v = eluf_(v);
        __nv_bfloat16 h = __float2bfloat16(v);
        __nv_bfloat16 l = __float2bfloat16(v - __bfloat162float(h));
        sAh[r * KP + k] = h;
        sAl[r * KP + k] = l;
    }
    __syncthreads();

    wmma::fragment<wmma::accumulator, 16, 16, 16, float> acc[R / 16];
#pragma unroll
    for (int nc = 0; nc < R / 16; nc++) wmma::fill_fragment(acc[nc], 0.f);

    int row0 = wid * 16;
#pragma unroll
    for (int kc = 0; kc < K / 16; kc++) {
        wmma::fragment<wmma::matrix_a, 16, 16, 16, __nv_bfloat16, wmma::row_major> ah, al;
        wmma::load_matrix_sync(ah, sAh + row0 * KP + kc * 16, KP);
        wmma::load_matrix_sync(al, sAl + row0 * KP + kc * 16, KP);
#pragma unroll
        for (int nc = 0; nc < R / 16; nc++) {
            wmma::fragment<wmma::matrix_b, 16, 16, 16, __nv_bfloat16, wmma::col_major> bh, bl;
            wmma::load_matrix_sync(bh, sBh + nc * 16 * KP + kc * 16, KP);
            wmma::load_matrix_sync(bl, sBh + R * KP + nc * 16 * KP + kc * 16, KP);
            wmma::mma_sync(acc[nc], ah, bh, acc[nc]);
            wmma::mma_sync(acc[nc], ah, bl, acc[nc]);
            wmma::mma_sync(acc[nc], al, bh, acc[nc]);
        }
    }

    // epilogue: per 16-col group through smem (ld=20), bias/act, guarded store
    __syncthreads();
#pragma unroll
    for (int nc = 0; nc < R / 16; nc++) {
        wmma::store_matrix_sync(sEp + row0 * 20, acc[nc], 20, wmma::mem_row_major);
        __syncthreads();
        for (int i = tid; i < 128 * 16; i += 256) {
            int r = i >> 4, c = i & 15;
            int nn = n0 + r;
            if (nn < N) {
                float v = sEp[r * 20 + c];
                if (bias) v += bias[nc * 16 + c];
                if (ACT == 1) v = eluf_(v);
                Y[(size_t)nn * R + nc * 16 + c] = v;
            }
        }
        __syncthreads();
    }
}

// ---------------- CSR gather-max ----------------
template <int C>
__global__ void k_gather(const float* __restrict__ m, const int* __restrict__ rowptr,
                         const int* __restrict__ esrc, const float* __restrict__ ews,
                         float* __restrict__ agg) {
    const int NPB = 256 / C;
    int c = threadIdx.x;
    int n = blockIdx.x * NPB + threadIdx.y;
    if (n >= N_NODES) return;
    int beg = rowptr[n], end = rowptr[n + 1];
    float acc0 = -INFINITY, acc1 = -INFINITY;
    int e = beg;
    for (; e + 1 < end; e += 2) {
        int   s0 = esrc[e], s1 = esrc[e + 1];
        float w0 = ews[e],  w1 = ews[e + 1];
        acc0 = fmaxf(acc0, m[(size_t)s0 * C + c] * w0);
        acc1 = fmaxf(acc1, m[(size_t)s1 * C + c] * w1);
    }
    if (e < end) acc0 = fmaxf(acc0, m[(size_t)esrc[e] * C + c] * ews[e]);
    float acc = fmaxf(acc0, acc1);
    agg[(size_t)n * C + c] = isfinite(acc) ? acc : 0.f;
}

// ---------------- GRU elementwise combine ----------------
template <int C>
__global__ void k_gru_comb(const float* __restrict__ gi, const float* __restrict__ gh,
                           float* __restrict__ h) {
    int i = blockIdx.x * blockDim.x + threadIdx.x;
    if (i >= N_NODES * C) return;
    int n = i / C, c = i - n * C;
    const float* gin = gi + (size_t)n * 3 * C;
    const float* ghn = gh + (size_t)n * 3 * C;
    float r  = sigmoidf_(gin[c]         + ghn[c]);
    float z  = sigmoidf_(gin[C + c]     + ghn[C + c]);
    float nn = tanhf    (gin[2 * C + c] + r * ghn[2 * C + c]);
    float hv = h[i];
    h[i] = (1.f - z) * nn + z * hv;
}

// ---------------- fc2 + log_softmax ----------------
__global__ void k_fc2_lsm(const float* __restrict__ X, const float* __restrict__ Wt,
                          const float* __restrict__ b, float* __restrict__ out) {
    int gt   = blockIdx.x * blockDim.x + threadIdx.x;
    int node = gt >> 5, lane = gt & 31;
    if (node >= N_NODES) return;
    const float* xr = X + (size_t)node * 128;
    float acc[10];
#pragma unroll
    for (int j = 0; j < 10; j++) acc[j] = 0.f;
    for (int k = lane; k < 128; k += 32) {
        float xv = xr[k];
        const float* w = Wt + k * 10;
#pragma unroll
        for (int j = 0; j < 10; j++) acc[j] = fmaf(xv, w[j], acc[j]);
    }
#pragma unroll
    for (int j = 0; j < 10; j++)
        for (int off = 16; off; off >>= 1) acc[j] += __shfl_xor_sync(0xffffffffu, acc[j], off);
    float mx = -INFINITY;
#pragma unroll
    for (int j = 0; j < 10; j++) { acc[j] += b[j]; mx = fmaxf(mx, acc[j]); }
    float se = 0.f;
#pragma unroll
    for (int j = 0; j < 10; j++) se += expf(acc[j] - mx);
    float lse = mx + logf(se);
    if (lane < 10) out[(size_t)node * 10 + lane] = acc[lane] - lse;
}

// ---------------- launch ----------------
static inline int gdiv(int n) { return (n + 255) / 256; }

extern "C" void kernel_launch(void* const* d_in, const int* in_sizes, int n_in,
                              void* d_out, int out_size) {
    const float* x    = (const float*)d_in[0];
    const void*  eraw = d_in[1];
    const float* ea   = (const float*)d_in[2];
    const float* W1   = (const float*)d_in[3];
    const float* Wih1 = (const float*)d_in[4];
    const float* Whh1 = (const float*)d_in[5];
    const float* bih1 = (const float*)d_in[6];
    const float* bhh1 = (const float*)d_in[7];
    const float* W2   = (const float*)d_in[8];
    const float* Wih2 = (const float*)d_in[9];
    const float* Whh2 = (const float*)d_in[10];
    const float* bih2 = (const float*)d_in[11];
    const float* bhh2 = (const float*)d_in[12];
    const float* fc1w = (const float*)d_in[13];
    const float* fc1b = (const float*)d_in[14];
    const float* fc2w = (const float*)d_in[15];
    const float* fc2b = (const float*)d_in[16];
    float* out = (float*)d_out;

    float *hA, *hB, *m, *agg, *gi, *gh, *hid, *fc2T, *ews;
    unsigned char* wimg;
    int *ei32, *deg, *rowptr, *cursor, *esrc;
    cudaGetSymbolAddress((void**)&hA,    g_hA);
    cudaGetSymbolAddress((void**)&hB,    g_hB);
    cudaGetSymbolAddress((void**)&m,     g_m);
    cudaGetSymbolAddress((void**)&agg,   g_agg);
    cudaGetSymbolAddress((void**)&gi,    g_gi);
    cudaGetSymbolAddress((void**)&gh,    g_gh);
    cudaGetSymbolAddress((void**)&hid,   g_hid);
    cudaGetSymbolAddress((void**)&fc2T,  g_fc2T);
    cudaGetSymbolAddress((void**)&wimg,  g_wimg);
    cudaGetSymbolAddress((void**)&ei32,  g_ei32);
    cudaGetSymbolAddress((void**)&deg,   g_deg);
    cudaGetSymbolAddress((void**)&rowptr,g_rowptr);
    cudaGetSymbolAddress((void**)&cursor,g_cursor);
    cudaGetSymbolAddress((void**)&esrc,  g_esrc);
    cudaGetSymbolAddress((void**)&ews,   g_ews);

    const int TB = 256;
    const int GM = (N_NODES + 127) / 128;   // 782

    // dynamic smem: (128 + R) * KP * 4 bytes
    const int SM_32_32  = (128 + 32)  * 40 * 4;   // 25600
    const int SM_32_96  = (128 + 96)  * 40 * 4;   // 35840
    const int SM_64_64  = (128 + 64)  * 72 * 4;   // 55296
    const int SM_64_192 = (128 + 192) * 72 * 4;   // 92160
    const int SM_64_128 = (128 + 128) * 72 * 4;   // 73728
    cudaFuncSetAttribute(tgemm<64, 64, 0>,  cudaFuncAttributeMaxDynamicSharedMemorySize, SM_64_64);
    cudaFuncSetAttribute(tgemm<64, 192, 0>, cudaFuncAttributeMaxDynamicSharedMemorySize, SM_64_192);
    cudaFuncSetAttribute(tgemm<64, 128, 1>, cudaFuncAttributeMaxDynamicSharedMemorySize, SM_64_128);

    // edge indices -> int32, CSR by destination
    k_sniff<<<1, 1024>>>(eraw);
    k_convert<<<gdiv(2 * N_EDGES), TB>>>(eraw, ei32);
    k_zero_i<<<gdiv(N_NODES), TB>>>(deg, N_NODES);
    k_count<<<gdiv(N_EDGES), TB>>>(ei32, deg);
    k_scan<<<1, 1024>>>(deg, rowptr);
    k_copy_i<<<gdiv(N_NODES), TB>>>(rowptr, cursor, N_NODES);
    k_place<<<gdiv(N_EDGES), TB>>>(ei32, ea, cursor, esrc, ews);

    // weight images (bf16 hi/lo, padded row-major [R][KP])
    for (int i = 0; i < 3; i++)
        k_prep_w<<<gdiv(32 * 40), TB>>>(W1 + i * 1024, wimg + OFF_W1 + i * 5120, 32, 32, 40, 1);
    k_prep_w<<<gdiv(96 * 40),  TB>>>(Wih1, wimg + OFF_WIH1, 96, 32, 40, 0);
    k_prep_w<<<gdiv(96 * 40),  TB>>>(Whh1, wimg + OFF_WHH1, 96, 32, 40, 0);
    for (int i = 0; i < 3; i++)
        k_prep_w<<<gdiv(64 * 72), TB>>>(W2 + i * 4096, wimg + OFF_W2 + i * 18432, 64, 64, 72, 1);
    k_prep_w<<<gdiv(192 * 72), TB>>>(Wih2, wimg + OFF_WIH2, 192, 64, 72, 0);
    k_prep_w<<<gdiv(192 * 72), TB>>>(Whh2, wimg + OFF_WHH2, 192, 64, 72, 0);
    k_prep_w<<<gdiv(128 * 72), TB>>>(fc1w, wimg + OFF_FC1, 128, 64, 72, 0);
    k_transpose<<<gdiv(10 * 128), TB>>>(fc2w, fc2T, 10, 128);

    // ---- layer 1 (C=32) ----
    k_init_h<<<gdiv(N_NODES * 32), TB>>>(x, hA);
    for (int i = 0; i < 3; i++) {
        tgemm<32, 32, 0><<<GM, 256, SM_32_32>>>(hA, wimg + OFF_W1 + i * 5120, nullptr, m, N_NODES, 0);
        { dim3 blk(32, 8); k_gather<32><<<(N_NODES + 7) / 8, blk>>>(m, rowptr, esrc, ews, agg); }
        tgemm<32, 96, 0><<<GM, 256, SM_32_96>>>(agg, wimg + OFF_WIH1, bih1, gi, N_NODES, 0);
        tgemm<32, 96, 0><<<GM, 256, SM_32_96>>>(hA,  wimg + OFF_WHH1, bhh1, gh, N_NODES, 0);
        k_gru_comb<32><<<gdiv(N_NODES * 32), TB>>>(gi, gh, hA);
    }

    k_pad_elu<<<gdiv(N_NODES * 64), TB>>>(hA, hB);

    // ---- layer 2 (C=64) ----
    for (int i = 0; i < 3; i++) {
        tgemm<64, 64, 0><<<GM, 256, SM_64_64>>>(hB, wimg + OFF_W2 + i * 18432, nullptr, m, N_NODES, 0);
        { dim3 blk(64, 4); k_gather<64><<<(N_NODES + 3) / 4, blk>>>(m, rowptr, esrc, ews, agg); }
        tgemm<64, 192, 0><<<GM, 256, SM_64_192>>>(agg, wimg + OFF_WIH2, bih2, gi, N_NODES, 0);
        tgemm<64, 192, 0><<<GM, 256, SM_64_192>>>(hB,  wimg + OFF_WHH2, bhh2, gh, N_NODES, 0);
        k_gru_comb<64><<<gdiv(N_NODES * 64), TB>>>(gi, gh, hB);
    }

    // ---- head: fc1 (input elu fused in staging, output elu), fc2 + log_softmax ----
    tgemm<64, 128, 1><<<GM, 256, SM_64_128>>>(hB, wimg + OFF_FC1, fc1b, hid, N_NODES, 1);
    k_fc2_lsm<<<gdiv(N_NODES * 32), TB>>>(hid, fc2T, fc2b, out);
}

// round 8
// speedup vs baseline: 1.6909x; 1.1598x over previous
#include <cuda_runtime.h>
#include <cuda_bf16.h>
#include <mma.h>
#include <math.h>
#include <stdint.h>

#define N_NODES 100000
#define N_EDGES 1600000

struct alignas(8) Edge { int s; float w; };

// ---------------- device scratch ----------------
__device__ float g_hA [N_NODES * 32];
__device__ float g_hB [N_NODES * 64];
__device__ float g_m  [N_NODES * 64];
__device__ float g_agg[N_NODES * 64];
__device__ float g_gi [N_NODES * 192];
__device__ float g_gh [N_NODES * 192];
__device__ float g_hid[N_NODES * 128];
__device__ float g_fc2T[128 * 10];
__device__ unsigned char g_wimg[262144];
__device__ int   g_ei32[2 * N_EDGES];
__device__ int   g_deg [N_NODES];
__device__ int   g_rowptr[N_NODES + 1];
__device__ int   g_cursor[N_NODES];
__device__ Edge  g_e2[N_EDGES];
__device__ int   g_bsum[128];
__device__ int   g_bsumex[128];
__device__ int   g_is64;

#define OFF_W1   0        // 3 x 5120   (R=32,KP=40)
#define OFF_WIH1 15360    // (R=96,KP=40)
#define OFF_WHH1 30720
#define OFF_W2   46080    // 3 x 18432  (R=64,KP=72)
#define OFF_WIH2 101376   // (R=192,KP=72)
#define OFF_WHH2 156672
#define OFF_FC1  211968   // (R=128,KP=72)

// ---------------- helpers ----------------
__device__ __forceinline__ float sigmoidf_(float x) { return 1.0f / (1.0f + expf(-x)); }
__device__ __forceinline__ float eluf_(float x)     { return x > 0.f ? x : expm1f(x); }

// ---------------- preprocessing ----------------
__global__ void k_sniff(const void* __restrict__ p) {
    __shared__ int s_bad;
    if (threadIdx.x == 0) s_bad = 0;
    __syncthreads();
    long long v = ((const long long*)p)[threadIdx.x];
    if (v < 0 || v >= N_NODES) atomicAdd(&s_bad, 1);
    __syncthreads();
    if (threadIdx.x == 0) g_is64 = (s_bad < 512) ? 1 : 0;
}

__global__ void k_convert(const void* __restrict__ p, int* __restrict__ out) {
    int i = blockIdx.x * blockDim.x + threadIdx.x;
    if (i >= 2 * N_EDGES) return;
    out[i] = g_is64 ? (int)((const long long*)p)[i] : ((const int*)p)[i];
}

__global__ void k_zero_i(int* __restrict__ p, int n) {
    int i = blockIdx.x * blockDim.x + threadIdx.x;
    if (i < n) p[i] = 0;
}

__global__ void k_count(const int* __restrict__ ei, int* __restrict__ deg) {
    int e = blockIdx.x * blockDim.x + threadIdx.x;
    if (e >= N_EDGES) return;
    int d = ei[N_EDGES + e];
    if ((unsigned)d < N_NODES) atomicAdd(&deg[d], 1);
}

// ---- multi-block scan ----
__global__ void k_scan1(const int* __restrict__ deg, int* __restrict__ rowptr,
                        int* __restrict__ bsum) {
    __shared__ int warp_sums[32];
    int tid = threadIdx.x, lane = tid & 31, wid = tid >> 5;
    int i = blockIdx.x * 1024 + tid;
    int v = (i < N_NODES) ? deg[i] : 0;
    int x = v;
#pragma unroll
    for (int d = 1; d < 32; d <<= 1) {
        int t = __shfl_up_sync(0xffffffffu, x, d);
        if (lane >= d) x += t;
    }
    if (lane == 31) warp_sums[wid] = x;
    __syncthreads();
    if (wid == 0) {
        int s = warp_sums[lane];
#pragma unroll
        for (int d = 1; d < 32; d <<= 1) {
            int t = __shfl_up_sync(0xffffffffu, s, d);
            if (lane >= d) s += t;
        }
        warp_sums[lane] = s;
    }
    __syncthreads();
    int pre = (wid > 0) ? warp_sums[wid - 1] : 0;
    if (i < N_NODES) rowptr[i] = pre + x - v;     // local exclusive
    if (tid == 1023) bsum[blockIdx.x] = pre + x;  // block total
}

__global__ void k_scan2(const int* __restrict__ bsum, int* __restrict__ bsumex,
                        int* __restrict__ rowptr, int nb) {
    __shared__ int warp_sums[4];
    int tid = threadIdx.x, lane = tid & 31, wid = tid >> 5;  // 128 threads
    int v = (tid < nb) ? bsum[tid] : 0;
    int x = v;
#pragma unroll
    for (int d = 1; d < 32; d <<= 1) {
        int t = __shfl_up_sync(0xffffffffu, x, d);
        if (lane >= d) x += t;
    }
    if (lane == 31) warp_sums[wid] = x;
    __syncthreads();
    int off = 0;
    for (int w = 0; w < wid; w++) off += warp_sums[w];
    if (tid < nb) bsumex[tid] = off + x - v;
    if (tid == 127) rowptr[N_NODES] = off + x;
}

__global__ void k_scan3(int* __restrict__ rowptr, const int* __restrict__ bsumex) {
    int i = blockIdx.x * blockDim.x + threadIdx.x;
    if (i < N_NODES) rowptr[i] += bsumex[i >> 10];
}

__global__ void k_copy_i(const int* __restrict__ a, int* __restrict__ b, int n) {
    int i = blockIdx.x * blockDim.x + threadIdx.x;
    if (i < n) b[i] = a[i];
}

__global__ void k_place(const int* __restrict__ ei, const float* __restrict__ ea,
                        int* __restrict__ cursor, Edge* __restrict__ e2) {
    int e = blockIdx.x * blockDim.x + threadIdx.x;
    if (e >= N_EDGES) return;
    int s = ei[e];
    int d = ei[N_EDGES + e];
    if ((unsigned)s >= N_NODES || (unsigned)d >= N_NODES) return;
    int pos = atomicAdd(&cursor[d], 1);
    Edge ed; ed.s = s; ed.w = ea[e];
    e2[pos] = ed;
}

// weight image prep
__global__ void k_prep_w(const float* __restrict__ src, unsigned char* __restrict__ dst,
                         int R, int K, int KP, int trans) {
    int idx = blockIdx.x * blockDim.x + threadIdx.x;
    if (idx >= R * KP) return;
    int r = idx / KP, k = idx - r * KP;
    float v = 0.f;
    if (k < K) v = trans ? src[k * R + r] : src[r * K + k];
    __nv_bfloat16 h = __float2bfloat16(v);
    __nv_bfloat16 l = __float2bfloat16(v - __bfloat162float(h));
    __nv_bfloat16* d16 = (__nv_bfloat16*)dst;
    d16[r * KP + k]          = h;
    d16[R * KP + r * KP + k] = l;
}

__global__ void k_transpose(const float* __restrict__ W, float* __restrict__ WT, int R, int K) {
    int idx = blockIdx.x * blockDim.x + threadIdx.x;
    if (idx < R * K) { int r = idx / K, k = idx - r * K; WT[k * R + r] = W[idx]; }
}

__global__ void k_init_h(const float* __restrict__ x, float* __restrict__ h) {
    int i = blockIdx.x * blockDim.x + threadIdx.x;
    if (i < N_NODES * 32) {
        int n = i >> 5, c = i & 31;
        h[i] = (c < 16) ? x[n * 16 + c] : 0.f;
    }
}

__global__ void k_pad_elu(const float* __restrict__ src, float* __restrict__ dst) {
    int i = blockIdx.x * blockDim.x + threadIdx.x;
    if (i < N_NODES * 64) {
        int n = i >> 6, c = i & 63;
        dst[i] = (c < 32) ? eluf_(src[n * 32 + c]) : 0.f;
    }
}

// ---------------- HMMA bf16x3 GEMM, R-chunked ----------------
// Computes Y[:, c0:c0+RC] for c0 = blockIdx.y*RC. B images full [R][KP] hi/lo.
template <int K, int RC, int ACT>
__global__ void __launch_bounds__(256)
tgemm(const float* __restrict__ X, const __nv_bfloat16* __restrict__ Bh,
      const __nv_bfloat16* __restrict__ Bl, const float* __restrict__ bias,
      float* __restrict__ Y, int N, int Rtot, int in_act) {
    using namespace nvcuda;
    constexpr int KP = K + 8;
    extern __shared__ unsigned char smem[];
    __nv_bfloat16* sAh = (__nv_bfloat16*)smem;            // 128*KP
    __nv_bfloat16* sAl = sAh + 128 * KP;
    __nv_bfloat16* sBh = sAl + 128 * KP;                  // RC*KP
    __nv_bfloat16* sBl = sBh + RC * KP;
    float* sEp = (float*)smem;                            // epilogue reuse

    int tid = threadIdx.x, wid = tid >> 5;
    int n0 = blockIdx.x * 128;
    int c0 = blockIdx.y * RC;

    // stage B chunk hi+lo
    {
        const uint4* bh = (const uint4*)(Bh + (size_t)c0 * KP);
        const uint4* bl = (const uint4*)(Bl + (size_t)c0 * KP);
        uint4* dh = (uint4*)sBh;
        uint4* dl = (uint4*)sBl;
        for (int i = tid; i < (RC * KP) / 8; i += 256) { dh[i] = bh[i]; dl[i] = bl[i]; }
    }
    // stage A: fp32 -> bf16 hi/lo
    for (int i = tid; i < 128 * K; i += 256) {
        int r = i / K, k = i - r * K;
        int nn = n0 + r;
        float v = (nn < N) ? X[(size_t)nn * K + k] : 0.f;
        if (in_act) v = eluf_(v);
        __nv_bfloat16 h = __float2bfloat16(v);
        __nv_bfloat16 l = __float2bfloat16(v - __bfloat162float(h));
        sAh[r * KP + k] = h;
        sAl[r * KP + k] = l;
    }
    __syncthreads();

    wmma::fragment<wmma::accumulator, 16, 16, 16, float> acc[RC / 16];
#pragma unroll
    for (int nc = 0; nc < RC / 16; nc++) wmma::fill_fragment(acc[nc], 0.f);

    int row0 = wid * 16;
#pragma unroll
    for (int kc = 0; kc < K / 16; kc++) {
        wmma::fragment<wmma::matrix_a, 16, 16, 16, __nv_bfloat16, wmma::row_major> ah, al;
        wmma::load_matrix_sync(ah, sAh + row0 * KP + kc * 16, KP);
        wmma::load_matrix_sync(al, sAl + row0 * KP + kc * 16, KP);
#pragma unroll
        for (int nc = 0; nc < RC / 16; nc++) {
            wmma::fragment<wmma::matrix_b, 16, 16, 16, __nv_bfloat16, wmma::col_major> bh, bl;
            wmma::load_matrix_sync(bh, sBh + nc * 16 * KP + kc * 16, KP);
            wmma::load_matrix_sync(bl, sBl + nc * 16 * KP + kc * 16, KP);
            wmma::mma_sync(acc[nc], ah, bh, acc[nc]);
            wmma::mma_sync(acc[nc], ah, bl, acc[nc]);
            wmma::mma_sync(acc[nc], al, bh, acc[nc]);
        }
    }

    __syncthreads();
#pragma unroll
    for (int nc = 0; nc < RC / 16; nc++) {
        wmma::store_matrix_sync(sEp + row0 * 20, acc[nc], 20, wmma::mem_row_major);
        __syncthreads();
        for (int i = tid; i < 128 * 16; i += 256) {
            int r = i >> 4, c = i & 15;
            int nn = n0 + r;
            if (nn < N) {
                float v = sEp[r * 20 + c];
                if (bias) v += bias[c0 + nc * 16 + c];
                if (ACT == 1) v = eluf_(v);
                Y[(size_t)nn * Rtot + c0 + nc * 16 + c] = v;
            }
        }
        __syncthreads();
    }
}

// ---------------- CSR gather-max (packed edges, 2 ch/thread) ----------------
template <int C>
__global__ void k_gather(const float* __restrict__ m, const int* __restrict__ rowptr,
                         const Edge* __restrict__ e2, float* __restrict__ agg) {
    int cx = threadIdx.x;                       // 0 .. C/2-1
    int n = blockIdx.x * blockDim.y + threadIdx.y;
    if (n >= N_NODES) return;
    int beg = rowptr[n], end = rowptr[n + 1];
    float2 a0 = make_float2(-INFINITY, -INFINITY);
    float2 a1 = make_float2(-INFINITY, -INFINITY);
    int e = beg;
    for (; e + 1 < end; e += 2) {
        Edge d0 = e2[e], d1 = e2[e + 1];
        float2 v0 = *(const float2*)&m[(size_t)d0.s * C + 2 * cx];
        float2 v1 = *(const float2*)&m[(size_t)d1.s * C + 2 * cx];
        a0.x = fmaxf(a0.x, v0.x * d0.w); a0.y = fmaxf(a0.y, v0.y * d0.w);
        a1.x = fmaxf(a1.x, v1.x * d1.w); a1.y = fmaxf(a1.y, v1.y * d1.w);
    }
    if (e < end) {
        Edge d0 = e2[e];
        float2 v0 = *(const float2*)&m[(size_t)d0.s * C + 2 * cx];
        a0.x = fmaxf(a0.x, v0.x * d0.w); a0.y = fmaxf(a0.y, v0.y * d0.w);
    }
    float2 r;
    r.x = fmaxf(a0.x, a1.x); r.y = fmaxf(a0.y, a1.y);
    if (!isfinite(r.x)) r.x = 0.f;
    if (!isfinite(r.y)) r.y = 0.f;
    *(float2*)&agg[(size_t)n * C + 2 * cx] = r;
}

// ---------------- GRU elementwise combine ----------------
template <int C>
__global__ void k_gru_comb(const float* __restrict__ gi, const float* __restrict__ gh,
                           float* __restrict__ h) {
    int i = blockIdx.x * blockDim.x + threadIdx.x;
    if (i >= N_NODES * C) return;
    int n = i / C, c = i - n * C;
    const float* gin = gi + (size_t)n * 3 * C;
    const float* ghn = gh + (size_t)n * 3 * C;
    float r  = sigmoidf_(gin[c]         + ghn[c]);
    float z  = sigmoidf_(gin[C + c]     + ghn[C + c]);
    float nn = tanhf    (gin[2 * C + c] + r * ghn[2 * C + c]);
    float hv = h[i];
    h[i] = (1.f - z) * nn + z * hv;
}

// ---------------- fc2 + log_softmax ----------------
__global__ void k_fc2_lsm(const float* __restrict__ X, const float* __restrict__ Wt,
                          const float* __restrict__ b, float* __restrict__ out) {
    int gt   = blockIdx.x * blockDim.x + threadIdx.x;
    int node = gt >> 5, lane = gt & 31;
    if (node >= N_NODES) return;
    const float* xr = X + (size_t)node * 128;
    float acc[10];
#pragma unroll
    for (int j = 0; j < 10; j++) acc[j] = 0.f;
    for (int k = lane; k < 128; k += 32) {
        float xv = xr[k];
        const float* w = Wt + k * 10;
#pragma unroll
        for (int j = 0; j < 10; j++) acc[j] = fmaf(xv, w[j], acc[j]);
    }
#pragma unroll
    for (int j = 0; j < 10; j++)
        for (int off = 16; off; off >>= 1) acc[j] += __shfl_xor_sync(0xffffffffu, acc[j], off);
    float mx = -INFINITY;
#pragma unroll
    for (int j = 0; j < 10; j++) { acc[j] += b[j]; mx = fmaxf(mx, acc[j]); }
    float se = 0.f;
#pragma unroll
    for (int j = 0; j < 10; j++) se += expf(acc[j] - mx);
    float lse = mx + logf(se);
    if (lane < 10) out[(size_t)node * 10 + lane] = acc[lane] - lse;
}

// ---------------- launch ----------------
static inline int gdiv(int n) { return (n + 255) / 256; }

extern "C" void kernel_launch(void* const* d_in, const int* in_sizes, int n_in,
                              void* d_out, int out_size) {
    const float* x    = (const float*)d_in[0];
    const void*  eraw = d_in[1];
    const float* ea   = (const float*)d_in[2];
    const float* W1   = (const float*)d_in[3];
    const float* Wih1 = (const float*)d_in[4];
    const float* Whh1 = (const float*)d_in[5];
    const float* bih1 = (const float*)d_in[6];
    const float* bhh1 = (const float*)d_in[7];
    const float* W2   = (const float*)d_in[8];
    const float* Wih2 = (const float*)d_in[9];
    const float* Whh2 = (const float*)d_in[10];
    const float* bih2 = (const float*)d_in[11];
    const float* bhh2 = (const float*)d_in[12];
    const float* fc1w = (const float*)d_in[13];
    const float* fc1b = (const float*)d_in[14];
    const float* fc2w = (const float*)d_in[15];
    const float* fc2b = (const float*)d_in[16];
    float* out = (float*)d_out;

    float *hA, *hB, *m, *agg, *gi, *gh, *hid, *fc2T;
    unsigned char* wimg;
    Edge* e2;
    int *ei32, *deg, *rowptr, *cursor, *bsum, *bsumex;
    cudaGetSymbolAddress((void**)&hA,    g_hA);
    cudaGetSymbolAddress((void**)&hB,    g_hB);
    cudaGetSymbolAddress((void**)&m,     g_m);
    cudaGetSymbolAddress((void**)&agg,   g_agg);
    cudaGetSymbolAddress((void**)&gi,    g_gi);
    cudaGetSymbolAddress((void**)&gh,    g_gh);
    cudaGetSymbolAddress((void**)&hid,   g_hid);
    cudaGetSymbolAddress((void**)&fc2T,  g_fc2T);
    cudaGetSymbolAddress((void**)&wimg,  g_wimg);
    cudaGetSymbolAddress((void**)&ei32,  g_ei32);
    cudaGetSymbolAddress((void**)&deg,   g_deg);
    cudaGetSymbolAddress((void**)&rowptr,g_rowptr);
    cudaGetSymbolAddress((void**)&cursor,g_cursor);
    cudaGetSymbolAddress((void**)&e2,    g_e2);
    cudaGetSymbolAddress((void**)&bsum,  g_bsum);
    cudaGetSymbolAddress((void**)&bsumex,g_bsumex);

    const int TB = 256;
    const int GM = (N_NODES + 127) / 128;   // 782
    const int NB = (N_NODES + 1023) / 1024; // 98

    // bf16 image pointers per matrix
    const __nv_bfloat16* W1h[3];  const __nv_bfloat16* W1l[3];
    const __nv_bfloat16* W2h[3];  const __nv_bfloat16* W2l[3];
    for (int i = 0; i < 3; i++) {
        W1h[i] = (const __nv_bfloat16*)(wimg + OFF_W1 + i * 5120);
        W1l[i] = W1h[i] + 32 * 40;
        W2h[i] = (const __nv_bfloat16*)(wimg + OFF_W2 + i * 18432);
        W2l[i] = W2h[i] + 64 * 72;
    }
    const __nv_bfloat16* Wih1h = (const __nv_bfloat16*)(wimg + OFF_WIH1);
    const __nv_bfloat16* Wih1l = Wih1h + 96 * 40;
    const __nv_bfloat16* Whh1h = (const __nv_bfloat16*)(wimg + OFF_WHH1);
    const __nv_bfloat16* Whh1l = Whh1h + 96 * 40;
    const __nv_bfloat16* Wih2h = (const __nv_bfloat16*)(wimg + OFF_WIH2);
    const __nv_bfloat16* Wih2l = Wih2h + 192 * 72;
    const __nv_bfloat16* Whh2h = (const __nv_bfloat16*)(wimg + OFF_WHH2);
    const __nv_bfloat16* Whh2l = Whh2h + 192 * 72;
    const __nv_bfloat16* Fc1h  = (const __nv_bfloat16*)(wimg + OFF_FC1);
    const __nv_bfloat16* Fc1l  = Fc1h + 128 * 72;

    // dynamic smem: (128 + RC) * KP * 4 bytes
    const int SM_32_32 = (128 + 32) * 40 * 4;   // 25600
    const int SM_32_48 = (128 + 48) * 40 * 4;   // 28160
    const int SM_64_64 = (128 + 64) * 72 * 4;   // 55296
    cudaFuncSetAttribute(tgemm<64, 64, 0>, cudaFuncAttributeMaxDynamicSharedMemorySize, SM_64_64);
    cudaFuncSetAttribute(tgemm<64, 64, 1>, cudaFuncAttributeMaxDynamicSharedMemorySize, SM_64_64);

    // edge indices -> int32, CSR by destination
    k_sniff<<<1, 1024>>>(eraw);
    k_convert<<<gdiv(2 * N_EDGES), TB>>>(eraw, ei32);
    k_zero_i<<<gdiv(N_NODES), TB>>>(deg, N_NODES);
    k_count<<<gdiv(N_EDGES), TB>>>(ei32, deg);
    k_scan1<<<NB, 1024>>>(deg, rowptr, bsum);
    k_scan2<<<1, 128>>>(bsum, bsumex, rowptr, NB);
    k_scan3<<<gdiv(N_NODES), TB>>>(rowptr, bsumex);
    k_copy_i<<<gdiv(N_NODES), TB>>>(rowptr, cursor, N_NODES);
    k_place<<<gdiv(N_EDGES), TB>>>(ei32, ea, cursor, e2);

    // weight images
    for (int i = 0; i < 3; i++)
        k_prep_w<<<gdiv(32 * 40), TB>>>(W1 + i * 1024, wimg + OFF_W1 + i * 5120, 32, 32, 40, 1);
    k_prep_w<<<gdiv(96 * 40),  TB>>>(Wih1, wimg + OFF_WIH1, 96, 32, 40, 0);
    k_prep_w<<<gdiv(96 * 40),  TB>>>(Whh1, wimg + OFF_WHH1, 96, 32, 40, 0);
    for (int i = 0; i < 3; i++)
        k_prep_w<<<gdiv(64 * 72), TB>>>(W2 + i * 4096, wimg + OFF_W2 + i * 18432, 64, 64, 72, 1);
    k_prep_w<<<gdiv(192 * 72), TB>>>(Wih2, wimg + OFF_WIH2, 192, 64, 72, 0);
    k_prep_w<<<gdiv(192 * 72), TB>>>(Whh2, wimg + OFF_WHH2, 192, 64, 72, 0);
    k_prep_w<<<gdiv(128 * 72), TB>>>(fc1w, wimg + OFF_FC1, 128, 64, 72, 0);
    k_transpose<<<gdiv(10 * 128), TB>>>(fc2w, fc2T, 10, 128);

    // ---- layer 1 (C=32) ----
    k_init_h<<<gdiv(N_NODES * 32), TB>>>(x, hA);
    for (int i = 0; i < 3; i++) {
        tgemm<32, 32, 0><<<dim3(GM, 1), 256, SM_32_32>>>(hA, W1h[i], W1l[i], nullptr, m, N_NODES, 32, 0);
        { dim3 blk(16, 16); k_gather<32><<<(N_NODES + 15) / 16, blk>>>(m, rowptr, e2, agg); }
        tgemm<32, 48, 0><<<dim3(GM, 2), 256, SM_32_48>>>(agg, Wih1h, Wih1l, bih1, gi, N_NODES, 96, 0);
        tgemm<32, 48, 0><<<dim3(GM, 2), 256, SM_32_48>>>(hA,  Whh1h, Whh1l, bhh1, gh, N_NODES, 96, 0);
        k_gru_comb<32><<<gdiv(N_NODES * 32), TB>>>(gi, gh, hA);
    }

    k_pad_elu<<<gdiv(N_NODES * 64), TB>>>(hA, hB);

    // ---- layer 2 (C=64) ----
    for (int i = 0; i < 3; i++) {
        tgemm<64, 64, 0><<<dim3(GM, 1), 256, SM_64_64>>>(hB, W2h[i], W2l[i], nullptr, m, N_NODES, 64, 0);
        { dim3 blk(32, 8); k_gather<64><<<(N_NODES + 7) / 8, blk>>>(m, rowptr, e2, agg); }
        tgemm<64, 64, 0><<<dim3(GM, 3), 256, SM_64_64>>>(agg, Wih2h, Wih2l, bih2, gi, N_NODES, 192, 0);
        tgemm<64, 64, 0><<<dim3(GM, 3), 256, SM_64_64>>>(hB,  Whh2h, Whh2l, bhh2, gh, N_NODES, 192, 0);
        k_gru_comb<64><<<gdiv(N_NODES * 64), TB>>>(gi, gh, hB);
    }

    // ---- head ----
    tgemm<64, 64, 1><<<dim3(GM, 2), 256, SM_64_64>>>(hB, Fc1h, Fc1l, fc1b, hid, N_NODES, 128, 1);
    k_fc2_lsm<<<gdiv(N_NODES * 32), TB>>>(hid, fc2T, fc2b, out);
}

// round 9
// speedup vs baseline: 1.9305x; 1.1417x over previous
#include <cuda_runtime.h>
#include <cuda_bf16.h>
#include <mma.h>
#include <math.h>
#include <stdint.h>

#define N_NODES 100000
#define N_EDGES 1600000

struct alignas(8) Edge { int s; float w; };

// ---------------- device scratch ----------------
__device__ float g_hA [N_NODES * 32];
__device__ float g_hB [N_NODES * 64];
__device__ float g_m  [N_NODES * 64];
__device__ float g_agg[N_NODES * 64];
__device__ float g_hid[N_NODES * 128];
__device__ float g_fc2T[128 * 10];
__device__ unsigned char g_wimg[262144];
__device__ int   g_ei32[2 * N_EDGES];
__device__ int   g_deg [N_NODES];
__device__ int   g_rowptr[N_NODES + 1];
__device__ int   g_cursor[N_NODES];
__device__ Edge  g_e2[N_EDGES];
__device__ int   g_bsum[128];
__device__ int   g_bsumex[128];
__device__ int   g_is64;

#define OFF_W1   0        // 3 x 5120   (R=32,KP=40)
#define OFF_WIH1 15360    // (R=96,KP=40)
#define OFF_WHH1 30720
#define OFF_W2   46080    // 3 x 18432  (R=64,KP=72)
#define OFF_WIH2 101376   // (R=192,KP=72)
#define OFF_WHH2 156672
#define OFF_FC1  211968   // (R=128,KP=72)

// ---------------- helpers ----------------
__device__ __forceinline__ float sigmoidf_(float x) { return 1.0f / (1.0f + expf(-x)); }
__device__ __forceinline__ float eluf_(float x)     { return x > 0.f ? x : expm1f(x); }

// ---------------- preprocessing ----------------
__global__ void k_sniff(const void* __restrict__ p) {
    __shared__ int s_bad;
    if (threadIdx.x == 0) s_bad = 0;
    __syncthreads();
    long long v = ((const long long*)p)[threadIdx.x];
    if (v < 0 || v >= N_NODES) atomicAdd(&s_bad, 1);
    __syncthreads();
    if (threadIdx.x == 0) g_is64 = (s_bad < 512) ? 1 : 0;
}

__global__ void k_convert(const void* __restrict__ p, int* __restrict__ out) {
    int i = blockIdx.x * blockDim.x + threadIdx.x;
    if (i >= 2 * N_EDGES) return;
    out[i] = g_is64 ? (int)((const long long*)p)[i] : ((const int*)p)[i];
}

__global__ void k_zero_i(int* __restrict__ p, int n) {
    int i = blockIdx.x * blockDim.x + threadIdx.x;
    if (i < n) p[i] = 0;
}

__global__ void k_count(const int* __restrict__ ei, int* __restrict__ deg) {
    int e = blockIdx.x * blockDim.x + threadIdx.x;
    if (e >= N_EDGES) return;
    int d = ei[N_EDGES + e];
    if ((unsigned)d < N_NODES) atomicAdd(&deg[d], 1);
}

// ---- multi-block scan ----
__global__ void k_scan1(const int* __restrict__ deg, int* __restrict__ rowptr,
                        int* __restrict__ bsum) {
    __shared__ int warp_sums[32];
    int tid = threadIdx.x, lane = tid & 31, wid = tid >> 5;
    int i = blockIdx.x * 1024 + tid;
    int v = (i < N_NODES) ? deg[i] : 0;
    int x = v;
#pragma unroll
    for (int d = 1; d < 32; d <<= 1) {
        int t = __shfl_up_sync(0xffffffffu, x, d);
        if (lane >= d) x += t;
    }
    if (lane == 31) warp_sums[wid] = x;
    __syncthreads();
    if (wid == 0) {
        int s = warp_sums[lane];
#pragma unroll
        for (int d = 1; d < 32; d <<= 1) {
            int t = __shfl_up_sync(0xffffffffu, s, d);
            if (lane >= d) s += t;
        }
        warp_sums[lane] = s;
    }
    __syncthreads();
    int pre = (wid > 0) ? warp_sums[wid - 1] : 0;
    if (i < N_NODES) rowptr[i] = pre + x - v;
    if (tid == 1023) bsum[blockIdx.x] = pre + x;
}

__global__ void k_scan2(const int* __restrict__ bsum, int* __restrict__ bsumex,
                        int* __restrict__ rowptr, int nb) {
    __shared__ int warp_sums[4];
    int tid = threadIdx.x, lane = tid & 31, wid = tid >> 5;
    int v = (tid < nb) ? bsum[tid] : 0;
    int x = v;
#pragma unroll
    for (int d = 1; d < 32; d <<= 1) {
        int t = __shfl_up_sync(0xffffffffu, x, d);
        if (lane >= d) x += t;
    }
    if (lane == 31) warp_sums[wid] = x;
    __syncthreads();
    int off = 0;
    for (int w = 0; w < wid; w++) off += warp_sums[w];
    if (tid < nb) bsumex[tid] = off + x - v;
    if (tid == 127) rowptr[N_NODES] = off + x;
}

__global__ void k_scan3(int* __restrict__ rowptr, const int* __restrict__ bsumex) {
    int i = blockIdx.x * blockDim.x + threadIdx.x;
    if (i < N_NODES) rowptr[i] += bsumex[i >> 10];
}

__global__ void k_copy_i(const int* __restrict__ a, int* __restrict__ b, int n) {
    int i = blockIdx.x * blockDim.x + threadIdx.x;
    if (i < n) b[i] = a[i];
}

__global__ void k_place(const int* __restrict__ ei, const float* __restrict__ ea,
                        int* __restrict__ cursor, Edge* __restrict__ e2) {
    int e = blockIdx.x * blockDim.x + threadIdx.x;
    if (e >= N_EDGES) return;
    int s = ei[e];
    int d = ei[N_EDGES + e];
    if ((unsigned)s >= N_NODES || (unsigned)d >= N_NODES) return;
    int pos = atomicAdd(&cursor[d], 1);
    Edge ed; ed.s = s; ed.w = ea[e];
    e2[pos] = ed;
}

// weight image prep: dst = [R][KP] bf16 hi image, lo image at +R*KP elems
__global__ void k_prep_w(const float* __restrict__ src, unsigned char* __restrict__ dst,
                         int R, int K, int KP, int trans) {
    int idx = blockIdx.x * blockDim.x + threadIdx.x;
    if (idx >= R * KP) return;
    int r = idx / KP, k = idx - r * KP;
    float v = 0.f;
    if (k < K) v = trans ? src[k * R + r] : src[r * K + k];
    __nv_bfloat16 h = __float2bfloat16(v);
    __nv_bfloat16 l = __float2bfloat16(v - __bfloat162float(h));
    __nv_bfloat16* d16 = (__nv_bfloat16*)dst;
    d16[r * KP + k]          = h;
    d16[R * KP + r * KP + k] = l;
}

__global__ void k_transpose(const float* __restrict__ W, float* __restrict__ WT, int R, int K) {
    int idx = blockIdx.x * blockDim.x + threadIdx.x;
    if (idx < R * K) { int r = idx / K, k = idx - r * K; WT[k * R + r] = W[idx]; }
}

__global__ void k_init_h(const float* __restrict__ x, float* __restrict__ h) {
    int i = blockIdx.x * blockDim.x + threadIdx.x;
    if (i < N_NODES * 32) {
        int n = i >> 5, c = i & 31;
        h[i] = (c < 16) ? x[n * 16 + c] : 0.f;
    }
}

__global__ void k_pad_elu(const float* __restrict__ src, float* __restrict__ dst) {
    int i = blockIdx.x * blockDim.x + threadIdx.x;
    if (i < N_NODES * 64) {
        int n = i >> 6, c = i & 63;
        dst[i] = (c < 32) ? eluf_(src[n * 32 + c]) : 0.f;
    }
}

// ---------------- HMMA bf16x3 GEMM, R-chunked (msg + fc1) ----------------
template <int K, int RC, int ACT>
__global__ void __launch_bounds__(256)
tgemm(const float* __restrict__ X, const __nv_bfloat16* __restrict__ Bh,
      const __nv_bfloat16* __restrict__ Bl, const float* __restrict__ bias,
      float* __restrict__ Y, int N, int Rtot, int in_act) {
    using namespace nvcuda;
    constexpr int KP = K + 8;
    extern __shared__ unsigned char smem[];
    __nv_bfloat16* sAh = (__nv_bfloat16*)smem;
    __nv_bfloat16* sAl = sAh + 128 * KP;
    __nv_bfloat16* sBh = sAl + 128 * KP;
    __nv_bfloat16* sBl = sBh + RC * KP;
    float* sEp = (float*)smem;

    int tid = threadIdx.x, wid = tid >> 5;
    int n0 = blockIdx.x * 128;
    int c0 = blockIdx.y * RC;

    {
        const uint4* bh = (const uint4*)(Bh + (size_t)c0 * KP);
        const uint4* bl = (const uint4*)(Bl + (size_t)c0 * KP);
        uint4* dh = (uint4*)sBh;
        uint4* dl = (uint4*)sBl;
        for (int i = tid; i < (RC * KP) / 8; i += 256) { dh[i] = bh[i]; dl[i] = bl[i]; }
    }
    for (int i = tid; i < 128 * K; i += 256) {
        int r = i / K, k = i - r * K;
        int nn = n0 + r;
        float v = (nn < N) ? X[(size_t)nn * K + k] : 0.f;
        if (in_act) v = eluf_(v);
        __nv_bfloat16 h = __float2bfloat16(v);
        __nv_bfloat16 l = __float2bfloat16(v - __bfloat162float(h));
        sAh[r * KP + k] = h;
        sAl[r * KP + k] = l;
    }
    __syncthreads();

    wmma::fragment<wmma::accumulator, 16, 16, 16, float> acc[RC / 16];
#pragma unroll
    for (int nc = 0; nc < RC / 16; nc++) wmma::fill_fragment(acc[nc], 0.f);

    int row0 = wid * 16;
#pragma unroll
    for (int kc = 0; kc < K / 16; kc++) {
        wmma::fragment<wmma::matrix_a, 16, 16, 16, __nv_bfloat16, wmma::row_major> ah, al;
        wmma::load_matrix_sync(ah, sAh + row0 * KP + kc * 16, KP);
        wmma::load_matrix_sync(al, sAl + row0 * KP + kc * 16, KP);
#pragma unroll
        for (int nc = 0; nc < RC / 16; nc++) {
            wmma::fragment<wmma::matrix_b, 16, 16, 16, __nv_bfloat16, wmma::col_major> bh, bl;
            wmma::load_matrix_sync(bh, sBh + nc * 16 * KP + kc * 16, KP);
            wmma::load_matrix_sync(bl, sBl + nc * 16 * KP + kc * 16, KP);
            wmma::mma_sync(acc[nc], ah, bh, acc[nc]);
            wmma::mma_sync(acc[nc], ah, bl, acc[nc]);
            wmma::mma_sync(acc[nc], al, bh, acc[nc]);
        }
    }

    __syncthreads();
#pragma unroll
    for (int nc = 0; nc < RC / 16; nc++) {
        wmma::store_matrix_sync(sEp + row0 * 20, acc[nc], 20, wmma::mem_row_major);
        __syncthreads();
        for (int i = tid; i < 128 * 16; i += 256) {
            int r = i >> 4, c = i & 15;
            int nn = n0 + r;
            if (nn < N) {
                float v = sEp[r * 20 + c];
                if (bias) v += bias[c0 + nc * 16 + c];
                if (ACT == 1) v = eluf_(v);
                Y[(size_t)nn * Rtot + c0 + nc * 16 + c] = v;
            }
        }
        __syncthreads();
    }
}

// ---------------- fused GRU: dual GEMM (agg@Wih^T, h@Whh^T) + combine ----------------
// CTA: 64 nodes, 128 threads (4 warps x 16 rows). Gate chunks of C columns:
// gate0 -> r (smem), gate1 -> z (smem), gate2 -> n + h' written to global.
template <int C>
__global__ void __launch_bounds__(128)
k_gru_mega(const float* __restrict__ agg, float* __restrict__ h,
           const __nv_bfloat16* __restrict__ Wih_h, const __nv_bfloat16* __restrict__ Wih_l,
           const __nv_bfloat16* __restrict__ Whh_h, const __nv_bfloat16* __restrict__ Whh_l,
           const float* __restrict__ bih, const float* __restrict__ bhh, int N) {
    using namespace nvcuda;
    constexpr int KP = C + 8;                 // bf16 row stride
    constexpr int LP = C + 8;                 // fp32 acc row stride
    constexpr int ABYTES = 4 * 64 * KP * 2;   // sAh,sAl,sHh,sHl
    constexpr int BBYTES = 4 * C * KP * 2;    // Bih hi/lo + Bhh hi/lo
    constexpr int GBYTES = 2 * 64 * LP * 4;   // gI, gH overlay
    constexpr int WBYTES = (BBYTES > GBYTES) ? BBYTES : GBYTES;
    extern __shared__ unsigned char smem[];
    __nv_bfloat16* sAh = (__nv_bfloat16*)smem;
    __nv_bfloat16* sAl = sAh + 64 * KP;
    __nv_bfloat16* sHh = sAl + 64 * KP;
    __nv_bfloat16* sHl = sHh + 64 * KP;
    unsigned char* wreg = smem + ABYTES;
    __nv_bfloat16* sBih_h = (__nv_bfloat16*)wreg;
    __nv_bfloat16* sBih_l = sBih_h + C * KP;
    __nv_bfloat16* sBhh_h = sBih_l + C * KP;
    __nv_bfloat16* sBhh_l = sBhh_h + C * KP;
    float* gI = (float*)wreg;
    float* gH = gI + 64 * LP;
    float* sR = (float*)(smem + ABYTES + WBYTES);
    float* sZ = sR + 64 * C;

    int tid = threadIdx.x, wid = tid >> 5;
    int n0 = blockIdx.x * 64;
    int row0 = wid * 16;

    // stage A (agg) and H (h), fp32 -> bf16 hi/lo
    for (int i = tid; i < 64 * C; i += 128) {
        int r = i / C, k = i - r * C;
        int nn = n0 + r;
        float va = (nn < N) ? agg[(size_t)nn * C + k] : 0.f;
        float vh = (nn < N) ? h[(size_t)nn * C + k] : 0.f;
        __nv_bfloat16 ah = __float2bfloat16(va);
        sAh[r * KP + k] = ah;
        sAl[r * KP + k] = __float2bfloat16(va - __bfloat162float(ah));
        __nv_bfloat16 hh = __float2bfloat16(vh);
        sHh[r * KP + k] = hh;
        sHl[r * KP + k] = __float2bfloat16(vh - __bfloat162float(hh));
    }
    __syncthreads();

#pragma unroll
    for (int g = 0; g < 3; g++) {
        // load gate-g weight chunks (rows g*C .. g*C+C-1)
        {
            const uint4* bih_h = (const uint4*)(Wih_h + (size_t)g * C * KP);
            const uint4* bih_l = (const uint4*)(Wih_l + (size_t)g * C * KP);
            const uint4* bhh_h = (const uint4*)(Whh_h + (size_t)g * C * KP);
            const uint4* bhh_l = (const uint4*)(Whh_l + (size_t)g * C * KP);
            uint4* d0 = (uint4*)sBih_h; uint4* d1 = (uint4*)sBih_l;
            uint4* d2 = (uint4*)sBhh_h; uint4* d3 = (uint4*)sBhh_l;
            for (int i = tid; i < (C * KP) / 8; i += 128) {
                d0[i] = bih_h[i]; d1[i] = bih_l[i];
                d2[i] = bhh_h[i]; d3[i] = bhh_l[i];
            }
        }
        __syncthreads();

        wmma::fragment<wmma::accumulator, 16, 16, 16, float> accI[C / 16], accH[C / 16];
#pragma unroll
        for (int nc = 0; nc < C / 16; nc++) {
            wmma::fill_fragment(accI[nc], 0.f);
            wmma::fill_fragment(accH[nc], 0.f);
        }
#pragma unroll
        for (int kc = 0; kc < C / 16; kc++) {
            wmma::fragment<wmma::matrix_a, 16, 16, 16, __nv_bfloat16, wmma::row_major> ah, al, hh, hl;
            wmma::load_matrix_sync(ah, sAh + row0 * KP + kc * 16, KP);
            wmma::load_matrix_sync(al, sAl + row0 * KP + kc * 16, KP);
            wmma::load_matrix_sync(hh, sHh + row0 * KP + kc * 16, KP);
            wmma::load_matrix_sync(hl, sHl + row0 * KP + kc * 16, KP);
#pragma unroll
            for (int nc = 0; nc < C / 16; nc++) {
                wmma::fragment<wmma::matrix_b, 16, 16, 16, __nv_bfloat16, wmma::col_major> bh, bl;
                wmma::load_matrix_sync(bh, sBih_h + nc * 16 * KP + kc * 16, KP);
                wmma::load_matrix_sync(bl, sBih_l + nc * 16 * KP + kc * 16, KP);
                wmma::mma_sync(accI[nc], ah, bh, accI[nc]);
                wmma::mma_sync(accI[nc], ah, bl, accI[nc]);
                wmma::mma_sync(accI[nc], al, bh, accI[nc]);
                wmma::load_matrix_sync(bh, sBhh_h + nc * 16 * KP + kc * 16, KP);
                wmma::load_matrix_sync(bl, sBhh_l + nc * 16 * KP + kc * 16, KP);
                wmma::mma_sync(accH[nc], hh, bh, accH[nc]);
                wmma::mma_sync(accH[nc], hh, bl, accH[nc]);
                wmma::mma_sync(accH[nc], hl, bh, accH[nc]);
            }
        }
        __syncthreads();   // all warps done reading B region

#pragma unroll
        for (int nc = 0; nc < C / 16; nc++) {
            wmma::store_matrix_sync(gI + row0 * LP + nc * 16, accI[nc], LP, wmma::mem_row_major);
            wmma::store_matrix_sync(gH + row0 * LP + nc * 16, accH[nc], LP, wmma::mem_row_major);
        }
        __syncthreads();

        for (int i = tid; i < 64 * C; i += 128) {
            int r = i / C, c = i - r * C;
            float vi = gI[r * LP + c] + bih[g * C + c];
            float vh = gH[r * LP + c] + bhh[g * C + c];
            if (g == 0) {
                sR[i] = sigmoidf_(vi + vh);
            } else if (g == 1) {
                sZ[i] = sigmoidf_(vi + vh);
            } else {
                int nn = n0 + r;
                if (nn < N) {
                    float rr = sR[i], zz = sZ[i];
                    float nv = tanhf(vi + rr * vh);
                    float hv = h[(size_t)nn * C + c];
                    h[(size_t)nn * C + c] = (1.f - zz) * nv + zz * hv;
                }
            }
        }
        __syncthreads();   // gI/gH consumed before next gate reloads B
    }
}

// ---------------- CSR gather-max (packed edges, 2 ch/thread, unroll 4) ----------------
template <int C>
__global__ void k_gather(const float* __restrict__ m, const int* __restrict__ rowptr,
                         const Edge* __restrict__ e2, float* __restrict__ agg) {
    int cx = threadIdx.x;
    int n = blockIdx.x * blockDim.y + threadIdx.y;
    if (n >= N_NODES) return;
    int beg = rowptr[n], end = rowptr[n + 1];
    float2 a0 = make_float2(-INFINITY, -INFINITY);
    float2 a1 = make_float2(-INFINITY, -INFINITY);
    float2 a2 = make_float2(-INFINITY, -INFINITY);
    float2 a3 = make_float2(-INFINITY, -INFINITY);
    int e = beg;
    for (; e + 3 < end; e += 4) {
        Edge d0 = e2[e], d1 = e2[e + 1], d2 = e2[e + 2], d3 = e2[e + 3];
        float2 v0 = *(const float2*)&m[(size_t)d0.s * C + 2 * cx];
        float2 v1 = *(const float2*)&m[(size_t)d1.s * C + 2 * cx];
        float2 v2 = *(const float2*)&m[(size_t)d2.s * C + 2 * cx];
        float2 v3 = *(const float2*)&m[(size_t)d3.s * C + 2 * cx];
        a0.x = fmaxf(a0.x, v0.x * d0.w); a0.y = fmaxf(a0.y, v0.y * d0.w);
        a1.x = fmaxf(a1.x, v1.x * d1.w); a1.y = fmaxf(a1.y, v1.y * d1.w);
        a2.x = fmaxf(a2.x, v2.x * d2.w); a2.y = fmaxf(a2.y, v2.y * d2.w);
        a3.x = fmaxf(a3.x, v3.x * d3.w); a3.y = fmaxf(a3.y, v3.y * d3.w);
    }
    for (; e < end; e++) {
        Edge d0 = e2[e];
        float2 v0 = *(const float2*)&m[(size_t)d0.s * C + 2 * cx];
        a0.x = fmaxf(a0.x, v0.x * d0.w); a0.y = fmaxf(a0.y, v0.y * d0.w);
    }
    float2 r;
    r.x = fmaxf(fmaxf(a0.x, a1.x), fmaxf(a2.x, a3.x));
    r.y = fmaxf(fmaxf(a0.y, a1.y), fmaxf(a2.y, a3.y));
    if (!isfinite(r.x)) r.x = 0.f;
    if (!isfinite(r.y)) r.y = 0.f;
    *(float2*)&agg[(size_t)n * C + 2 * cx] = r;
}

// ---------------- fc2 + log_softmax ----------------
__global__ void k_fc2_lsm(const float* __restrict__ X, const float* __restrict__ Wt,
                          const float* __restrict__ b, float* __restrict__ out) {
    int gt   = blockIdx.x * blockDim.x + threadIdx.x;
    int node = gt >> 5, lane = gt & 31;
    if (node >= N_NODES) return;
    const float* xr = X + (size_t)node * 128;
    float acc[10];
#pragma unroll
    for (int j = 0; j < 10; j++) acc[j] = 0.f;
    for (int k = lane; k < 128; k += 32) {
        float xv = xr[k];
        const float* w = Wt + k * 10;
#pragma unroll
        for (int j = 0; j < 10; j++) acc[j] = fmaf(xv, w[j], acc[j]);
    }
#pragma unroll
    for (int j = 0; j < 10; j++)
        for (int off = 16; off; off >>= 1) acc[j] += __shfl_xor_sync(0xffffffffu, acc[j], off);
    float mx = -INFINITY;
#pragma unroll
    for (int j = 0; j < 10; j++) { acc[j] += b[j]; mx = fmaxf(mx, acc[j]); }
    float se = 0.f;
#pragma unroll
    for (int j = 0; j < 10; j++) se += expf(acc[j] - mx);
    float lse = mx + logf(se);
    if (lane < 10) out[(size_t)node * 10 + lane] = acc[lane] - lse;
}

// ---------------- launch ----------------
static inline int gdiv(int n) { return (n + 255) / 256; }

extern "C" void kernel_launch(void* const* d_in, const int* in_sizes, int n_in,
                              void* d_out, int out_size) {
    const float* x    = (const float*)d_in[0];
    const void*  eraw = d_in[1];
    const float* ea   = (const float*)d_in[2];
    const float* W1   = (const float*)d_in[3];
    const float* Wih1 = (const float*)d_in[4];
    const float* Whh1 = (const float*)d_in[5];
    const float* bih1 = (const float*)d_in[6];
    const float* bhh1 = (const float*)d_in[7];
    const float* W2   = (const float*)d_in[8];
    const float* Wih2 = (const float*)d_in[9];
    const float* Whh2 = (const float*)d_in[10];
    const float* bih2 = (const float*)d_in[11];
    const float* bhh2 = (const float*)d_in[12];
    const float* fc1w = (const float*)d_in[13];
    const float* fc1b = (const float*)d_in[14];
    const float* fc2w = (const float*)d_in[15];
    const float* fc2b = (const float*)d_in[16];
    float* out = (float*)d_out;

    float *hA, *hB, *m, *agg, *hid, *fc2T;
    unsigned char* wimg;
    Edge* e2;
    int *ei32, *deg, *rowptr, *cursor, *bsum, *bsumex;
    cudaGetSymbolAddress((void**)&hA,    g_hA);
    cudaGetSymbolAddress((void**)&hB,    g_hB);
    cudaGetSymbolAddress((void**)&m,     g_m);
    cudaGetSymbolAddress((void**)&agg,   g_agg);
    cudaGetSymbolAddress((void**)&hid,   g_hid);
    cudaGetSymbolAddress((void**)&fc2T,  g_fc2T);
    cudaGetSymbolAddress((void**)&wimg,  g_wimg);
    cudaGetSymbolAddress((void**)&ei32,  g_ei32);
    cudaGetSymbolAddress((void**)&deg,   g_deg);
    cudaGetSymbolAddress((void**)&rowptr,g_rowptr);
    cudaGetSymbolAddress((void**)&cursor,g_cursor);
    cudaGetSymbolAddress((void**)&e2,    g_e2);
    cudaGetSymbolAddress((void**)&bsum,  g_bsum);
    cudaGetSymbolAddress((void**)&bsumex,g_bsumex);

    const int TB = 256;
    const int GM  = (N_NODES + 127) / 128;  // 782
    const int GM64 = (N_NODES + 63) / 64;   // 1563
    const int NB = (N_NODES + 1023) / 1024; // 98

    const __nv_bfloat16* W1h[3];  const __nv_bfloat16* W1l[3];
    const __nv_bfloat16* W2h[3];  const __nv_bfloat16* W2l[3];
    for (int i = 0; i < 3; i++) {
        W1h[i] = (const __nv_bfloat16*)(wimg + OFF_W1 + i * 5120);
        W1l[i] = W1h[i] + 32 * 40;
        W2h[i] = (const __nv_bfloat16*)(wimg + OFF_W2 + i * 18432);
        W2l[i] = W2h[i] + 64 * 72;
    }
    const __nv_bfloat16* Wih1h = (const __nv_bfloat16*)(wimg + OFF_WIH1);
    const __nv_bfloat16* Wih1l = Wih1h + 96 * 40;
    const __nv_bfloat16* Whh1h = (const __nv_bfloat16*)(wimg + OFF_WHH1);
    const __nv_bfloat16* Whh1l = Whh1h + 96 * 40;
    const __nv_bfloat16* Wih2h = (const __nv_bfloat16*)(wimg + OFF_WIH2);
    const __nv_bfloat16* Wih2l = Wih2h + 192 * 72;
    const __nv_bfloat16* Whh2h = (const __nv_bfloat16*)(wimg + OFF_WHH2);
    const __nv_bfloat16* Whh2l = Whh2h + 192 * 72;
    const __nv_bfloat16* Fc1h  = (const __nv_bfloat16*)(wimg + OFF_FC1);
    const __nv_bfloat16* Fc1l  = Fc1h + 128 * 72;

    // dynamic smem sizes
    const int SM_32_32 = (128 + 32) * 40 * 4;       // tgemm msg L1
    const int SM_64_64 = (128 + 64) * 72 * 4;       // tgemm msg L2 / fc1: 55296
    const int MEGA32 = 4 * 64 * 40 * 2 + 2 * 64 * 40 * 4 + 2 * 64 * 32 * 4;   // 57344
    const int MEGA64 = 4 * 64 * 72 * 2 + 4 * 64 * 72 * 2 + 2 * 64 * 64 * 4;   // 106496
    cudaFuncSetAttribute(tgemm<64, 64, 0>, cudaFuncAttributeMaxDynamicSharedMemorySize, SM_64_64);
    cudaFuncSetAttribute(tgemm<64, 64, 1>, cudaFuncAttributeMaxDynamicSharedMemorySize, SM_64_64);
    cudaFuncSetAttribute(k_gru_mega<32>, cudaFuncAttributeMaxDynamicSharedMemorySize, MEGA32);
    cudaFuncSetAttribute(k_gru_mega<64>, cudaFuncAttributeMaxDynamicSharedMemorySize, MEGA64);

    // edge indices -> int32, CSR by destination
    k_sniff<<<1, 1024>>>(eraw);
    k_convert<<<gdiv(2 * N_EDGES), TB>>>(eraw, ei32);
    k_zero_i<<<gdiv(N_NODES), TB>>>(deg, N_NODES);
    k_count<<<gdiv(N_EDGES), TB>>>(ei32, deg);
    k_scan1<<<NB, 1024>>>(deg, rowptr, bsum);
    k_scan2<<<1, 128>>>(bsum, bsumex, rowptr, NB);
    k_scan3<<<gdiv(N_NODES), TB>>>(rowptr, bsumex);
    k_copy_i<<<gdiv(N_NODES), TB>>>(rowptr, cursor, N_NODES);
    k_place<<<gdiv(N_EDGES), TB>>>(ei32, ea, cursor, e2);

    // weight images
    for (int i = 0; i < 3; i++)
        k_prep_w<<<gdiv(32 * 40), TB>>>(W1 + i * 1024, wimg + OFF_W1 + i * 5120, 32, 32, 40, 1);
    k_prep_w<<<gdiv(96 * 40),  TB>>>(Wih1, wimg + OFF_WIH1, 96, 32, 40, 0);
    k_prep_w<<<gdiv(96 * 40),  TB>>>(Whh1, wimg + OFF_WHH1, 96, 32, 40, 0);
    for (int i = 0; i < 3; i++)
        k_prep_w<<<gdiv(64 * 72), TB>>>(W2 + i * 4096, wimg + OFF_W2 + i * 18432, 64, 64, 72, 1);
    k_prep_w<<<gdiv(192 * 72), TB>>>(Wih2, wimg + OFF_WIH2, 192, 64, 72, 0);
    k_prep_w<<<gdiv(192 * 72), TB>>>(Whh2, wimg + OFF_WHH2, 192, 64, 72, 0);
    k_prep_w<<<gdiv(128 * 72), TB>>>(fc1w, wimg + OFF_FC1, 128, 64, 72, 0);
    k_transpose<<<gdiv(10 * 128), TB>>>(fc2w, fc2T, 10, 128);

    // ---- layer 1 (C=32) ----
    k_init_h<<<gdiv(N_NODES * 32), TB>>>(x, hA);
    for (int i = 0; i < 3; i++) {
        tgemm<32, 32, 0><<<dim3(GM, 1), 256, SM_32_32>>>(hA, W1h[i], W1l[i], nullptr, m, N_NODES, 32, 0);
        { dim3 blk(16, 16); k_gather<32><<<(N_NODES + 15) / 16, blk>>>(m, rowptr, e2, agg); }
        k_gru_mega<32><<<GM64, 128, MEGA32>>>(agg, hA, Wih1h, Wih1l, Whh1h, Whh1l, bih1, bhh1, N_NODES);
    }

    k_pad_elu<<<gdiv(N_NODES * 64), TB>>>(hA, hB);

    // ---- layer 2 (C=64) ----
    for (int i = 0; i < 3; i++) {
        tgemm<64, 64, 0><<<dim3(GM, 1), 256, SM_64_64>>>(hB, W2h[i], W2l[i], nullptr, m, N_NODES, 64, 0);
        { dim3 blk(32, 8); k_gather<64><<<(N_NODES + 7) / 8, blk>>>(m, rowptr, e2, agg); }
        k_gru_mega<64><<<GM64, 128, MEGA64>>>(agg, hB, Wih2h, Wih2l, Whh2h, Whh2l, bih2, bhh2, N_NODES);
    }

    // ---- head ----
    tgemm<64, 64, 1><<<dim3(GM, 2), 256, SM_64_64>>>(hB, Fc1h, Fc1l, fc1b, hid, N_NODES, 128, 1);
    k_fc2_lsm<<<gdiv(N_NODES * 32), TB>>>(hid, fc2T, fc2b, out);
}